// round 1
// baseline (speedup 1.0000x reference)
#include <cuda_runtime.h>

#define SCALE       0.35355339059327373f   // 64^(-1/4)
#define INV_SQRT_M  0.08838834764831843f   // 1/sqrt(128)
#define EPS_PHI     1e-4f
#define EPS_DEN     1e-6f

#define BH    64        // B*H = 4*16
#define Nn    4096
#define Dd    64
#define Mm    128
#define CH    128       // chunk length
#define NC    32        // chunks per head
#define NTOK  (BH*Nn)   // 262144
#define NBT   (NTOK/CH) // 2048 token-chunks

// Scratch (static __device__ — no allocations allowed)
__device__ float d_phiq[(size_t)NTOK*Mm];   // phi_q  [tok][m]
__device__ float d_phik[(size_t)NTOK*Mm];   // log-phi_k, then phi_k in place
__device__ float d_S[(size_t)BH*NC*Mm*Dd];  // chunk sums -> exclusive prefix states
__device__ float d_zz[BH*NC*Mm];            // chunk z sums -> exclusive prefix
__device__ float d_bmax[NBT];
__device__ float d_gmax;

// ---------------------------------------------------------------------------
// K1: proj = (x*scale) @ omega^T for q and k chunks.
//  q: finalize phi_q = exp(proj - rowmax(proj))/sqrt(M)+eps  (the -0.5||x||^2
//     cancels under the per-row max) and store.
//  k: store lp = proj - 0.5||x||^2, record block max for the global max.
// smem: xsT[64][132] omT[64][132] ss[128] red[2048]  (76288 B)
// ---------------------------------------------------------------------------
__global__ __launch_bounds__(256) void k_proj(const float* __restrict__ qg,
                                              const float* __restrict__ kg,
                                              const float* __restrict__ omg) {
    extern __shared__ float sm[];
    float* xsT = sm;               // [64][132]
    float* omT = sm + 64*132;      // [64][132]
    float* ss  = sm + 2*64*132;    // [128]
    float* red = ss + 128;         // [2048]

    const int bid = blockIdx.x;
    const bool isq = bid < NBT;
    const int tb  = isq ? bid : bid - NBT;
    const float* xg = (isq ? qg : kg) + (size_t)tb * CH * Dd;
    const int tid = threadIdx.x;

    // load x chunk [128][64] -> xsT[d][i] (scaled)
    #pragma unroll
    for (int rep = 0; rep < 8; rep++) {
        int idx = rep*256 + tid;
        int i  = idx >> 4;
        int d4 = (idx & 15) << 2;
        float4 t = *reinterpret_cast<const float4*>(xg + i*Dd + d4);
        xsT[(d4+0)*132 + i] = t.x * SCALE;
        xsT[(d4+1)*132 + i] = t.y * SCALE;
        xsT[(d4+2)*132 + i] = t.z * SCALE;
        xsT[(d4+3)*132 + i] = t.w * SCALE;
    }
    // omega [128][64] -> omT[d][m]
    #pragma unroll
    for (int rep = 0; rep < 8; rep++) {
        int idx = rep*256 + tid;
        int m  = idx >> 4;
        int d4 = (idx & 15) << 2;
        float4 t = *reinterpret_cast<const float4*>(omg + m*Dd + d4);
        omT[(d4+0)*132 + m] = t.x;
        omT[(d4+1)*132 + m] = t.y;
        omT[(d4+2)*132 + m] = t.z;
        omT[(d4+3)*132 + m] = t.w;
    }
    __syncthreads();
    if (tid < 128) {
        float s = 0.f;
        #pragma unroll
        for (int d = 0; d < 64; d++) { float vv = xsT[d*132 + tid]; s = fmaf(vv, vv, s); }
        ss[tid] = 0.5f * s;
    }
    __syncthreads();

    const int tx = tid & 15, ty = tid >> 4;
    const int i0 = ty*8, m0 = tx*8;
    float acc[8][8];
    #pragma unroll
    for (int u = 0; u < 8; u++)
        #pragma unroll
        for (int w = 0; w < 8; w++) acc[u][w] = 0.f;

    for (int d = 0; d < 64; d++) {
        float a[8], b[8];
        float4 t;
        t = *reinterpret_cast<const float4*>(&xsT[d*132 + i0]);     a[0]=t.x;a[1]=t.y;a[2]=t.z;a[3]=t.w;
        t = *reinterpret_cast<const float4*>(&xsT[d*132 + i0 + 4]); a[4]=t.x;a[5]=t.y;a[6]=t.z;a[7]=t.w;
        t = *reinterpret_cast<const float4*>(&omT[d*132 + m0]);     b[0]=t.x;b[1]=t.y;b[2]=t.z;b[3]=t.w;
        t = *reinterpret_cast<const float4*>(&omT[d*132 + m0 + 4]); b[4]=t.x;b[5]=t.y;b[6]=t.z;b[7]=t.w;
        #pragma unroll
        for (int u = 0; u < 8; u++)
            #pragma unroll
            for (int w = 0; w < 8; w++) acc[u][w] = fmaf(a[u], b[w], acc[u][w]);
    }

    const size_t tok0 = (size_t)tb * CH;
    if (isq) {
        #pragma unroll
        for (int u = 0; u < 8; u++) {
            float m = acc[u][0];
            #pragma unroll
            for (int w = 1; w < 8; w++) m = fmaxf(m, acc[u][w]);
            red[(i0+u)*16 + tx] = m;
        }
        __syncthreads();
        if (tid < 128) {
            float m = red[tid*16];
            #pragma unroll
            for (int t = 1; t < 16; t++) m = fmaxf(m, red[tid*16 + t]);
            ss[tid] = m;   // reuse as rowmax
        }
        __syncthreads();
        float* og = d_phiq + tok0 * Mm;
        #pragma unroll
        for (int u = 0; u < 8; u++) {
            float rm = ss[i0+u];
            float4 s0, s1;
            s0.x = __expf(acc[u][0]-rm)*INV_SQRT_M + EPS_PHI;
            s0.y = __expf(acc[u][1]-rm)*INV_SQRT_M + EPS_PHI;
            s0.z = __expf(acc[u][2]-rm)*INV_SQRT_M + EPS_PHI;
            s0.w = __expf(acc[u][3]-rm)*INV_SQRT_M + EPS_PHI;
            s1.x = __expf(acc[u][4]-rm)*INV_SQRT_M + EPS_PHI;
            s1.y = __expf(acc[u][5]-rm)*INV_SQRT_M + EPS_PHI;
            s1.z = __expf(acc[u][6]-rm)*INV_SQRT_M + EPS_PHI;
            s1.w = __expf(acc[u][7]-rm)*INV_SQRT_M + EPS_PHI;
            *reinterpret_cast<float4*>(og + (size_t)(i0+u)*Mm + m0)     = s0;
            *reinterpret_cast<float4*>(og + (size_t)(i0+u)*Mm + m0 + 4) = s1;
        }
    } else {
        float bm = -3.0e38f;
        float* og = d_phik + tok0 * Mm;
        #pragma unroll
        for (int u = 0; u < 8; u++) {
            float sr = ss[i0+u];
            #pragma unroll
            for (int w = 0; w < 8; w++) { acc[u][w] -= sr; bm = fmaxf(bm, acc[u][w]); }
            float4 s0, s1;
            s0.x=acc[u][0]; s0.y=acc[u][1]; s0.z=acc[u][2]; s0.w=acc[u][3];
            s1.x=acc[u][4]; s1.y=acc[u][5]; s1.z=acc[u][6]; s1.w=acc[u][7];
            *reinterpret_cast<float4*>(og + (size_t)(i0+u)*Mm + m0)     = s0;
            *reinterpret_cast<float4*>(og + (size_t)(i0+u)*Mm + m0 + 4) = s1;
        }
        red[tid] = bm;
        __syncthreads();
        for (int s = 128; s > 0; s >>= 1) {
            if (tid < s) red[tid] = fmaxf(red[tid], red[tid+s]);
            __syncthreads();
        }
        if (tid == 0) d_bmax[tb] = red[0];
    }
}

// K1b: reduce block maxima -> d_gmax
__global__ __launch_bounds__(256) void k_gmax() {
    __shared__ float red[256];
    const int tid = threadIdx.x;
    float m = -3.0e38f;
    for (int i = tid; i < NBT; i += 256) m = fmaxf(m, d_bmax[i]);
    red[tid] = m;
    __syncthreads();
    for (int s = 128; s > 0; s >>= 1) {
        if (tid < s) red[tid] = fmaxf(red[tid], red[tid+s]);
        __syncthreads();
    }
    if (tid == 0) d_gmax = red[0];
}

// ---------------------------------------------------------------------------
// K2: phi_k = exp(lp - gmax)/sqrt(M)+eps (written back); chunk Ssum = phi_k^T V,
// zsum = colsum(phi_k).  smem: phis[128][128] vs[128][64]  (98304 B)
// ---------------------------------------------------------------------------
__global__ __launch_bounds__(256) void k_phik_sums(const float* __restrict__ vg) {
    extern __shared__ float sm[];
    float* phis = sm;            // [128][128]
    float* vs   = sm + 128*128;  // [128][64]
    const int bid = blockIdx.x;
    const int bh = bid >> 5, c = bid & 31;
    const size_t tok0 = (size_t)bh * Nn + (size_t)c * CH;
    const int tid = threadIdx.x;
    const float gm = d_gmax;

    float* pk = d_phik + tok0 * Mm;
    #pragma unroll
    for (int rep = 0; rep < 16; rep++) {
        int idx = (rep*256 + tid) * 4;
        float4 t = *reinterpret_cast<const float4*>(pk + idx);
        t.x = __expf(t.x-gm)*INV_SQRT_M + EPS_PHI;
        t.y = __expf(t.y-gm)*INV_SQRT_M + EPS_PHI;
        t.z = __expf(t.z-gm)*INV_SQRT_M + EPS_PHI;
        t.w = __expf(t.w-gm)*INV_SQRT_M + EPS_PHI;
        *reinterpret_cast<float4*>(pk + idx)   = t;
        *reinterpret_cast<float4*>(phis + idx) = t;
    }
    #pragma unroll
    for (int rep = 0; rep < 8; rep++) {
        int idx = (rep*256 + tid) * 4;
        *reinterpret_cast<float4*>(vs + idx) =
            *reinterpret_cast<const float4*>(vg + tok0*Dd + idx);
    }
    __syncthreads();

    const int tx = tid & 15, ty = tid >> 4;
    const int m0 = ty*8, d0 = tx*4;
    float acc[8][4];
    float zacc[8];
    #pragma unroll
    for (int u = 0; u < 8; u++) {
        zacc[u] = 0.f;
        #pragma unroll
        for (int w = 0; w < 4; w++) acc[u][w] = 0.f;
    }
    for (int i = 0; i < 128; i++) {
        float a[8];
        float4 t;
        t = *reinterpret_cast<const float4*>(&phis[i*128 + m0]);     a[0]=t.x;a[1]=t.y;a[2]=t.z;a[3]=t.w;
        t = *reinterpret_cast<const float4*>(&phis[i*128 + m0 + 4]); a[4]=t.x;a[5]=t.y;a[6]=t.z;a[7]=t.w;
        float4 b = *reinterpret_cast<const float4*>(&vs[i*64 + d0]);
        #pragma unroll
        for (int u = 0; u < 8; u++) {
            acc[u][0] = fmaf(a[u], b.x, acc[u][0]);
            acc[u][1] = fmaf(a[u], b.y, acc[u][1]);
            acc[u][2] = fmaf(a[u], b.z, acc[u][2]);
            acc[u][3] = fmaf(a[u], b.w, acc[u][3]);
        }
        if (tx == 0) {
            #pragma unroll
            for (int u = 0; u < 8; u++) zacc[u] += a[u];
        }
    }
    float* Sg = d_S + (size_t)(bh*NC + c) * (Mm*Dd);
    #pragma unroll
    for (int u = 0; u < 8; u++) {
        float4 t; t.x=acc[u][0]; t.y=acc[u][1]; t.z=acc[u][2]; t.w=acc[u][3];
        *reinterpret_cast<float4*>(Sg + (m0+u)*Dd + d0) = t;
    }
    if (tx == 0) {
        float* zg = d_zz + (bh*NC + c) * Mm;
        #pragma unroll
        for (int u = 0; u < 8; u++) zg[m0+u] = zacc[u];
    }
}

// ---------------------------------------------------------------------------
// K3: exclusive prefix over the 32 chunks (per head), in place.
// ---------------------------------------------------------------------------
__global__ __launch_bounds__(256) void k_scan() {
    const int bh = blockIdx.x;
    const int tid = threadIdx.x;
    const size_t base = (size_t)bh * NC * (Mm*Dd);
    for (int e = tid; e < Mm*Dd; e += 256) {
        float acc = 0.f;
        size_t p = base + e;
        #pragma unroll 4
        for (int c = 0; c < NC; c++, p += Mm*Dd) {
            float t = d_S[p]; d_S[p] = acc; acc += t;
        }
    }
    if (tid < Mm) {
        float acc = 0.f;
        size_t p = (size_t)bh * NC * Mm + tid;
        #pragma unroll 4
        for (int c = 0; c < NC; c++, p += Mm) {
            float t = d_zz[p]; d_zz[p] = acc; acc += t;
        }
    }
}

// ---------------------------------------------------------------------------
// K4: A = phi_q phi_k^T (causal mask), out = (A V + phi_q S_prev) / den
// smem: pqT[128][132] pkA[128][132] vs[128][64] Ss[128][64] zs den dp (209920 B)
// ---------------------------------------------------------------------------
__global__ __launch_bounds__(256) void k_out(const float* __restrict__ vg,
                                             float* __restrict__ outg) {
    extern __shared__ float sm[];
    float* pqT = sm;                   // [128][132]  pqT[m][i]
    float* pkA = sm + 128*132;         // [128][132]  pkT[m][j] then AT[j][i]
    float* vs  = sm + 2*128*132;       // [128][64]
    float* Ss  = vs + 128*64;          // [128][64]
    float* zs  = Ss + 128*64;          // [128]
    float* den = zs + 128;             // [128]
    float* dp  = den + 128;            // [128*16]

    const int bid = blockIdx.x;
    const int bh = bid >> 5, c = bid & 31;
    const size_t tok0 = (size_t)bh * Nn + (size_t)c * CH;
    const int tid = threadIdx.x;

    const float* pqg = d_phiq + tok0 * Mm;
    const float* pkg = d_phik + tok0 * Mm;
    #pragma unroll
    for (int rep = 0; rep < 16; rep++) {
        int f = (rep*256 + tid) * 4;
        int i = f >> 7, m = f & 127;
        float4 t = *reinterpret_cast<const float4*>(pqg + f);
        pqT[(m+0)*132 + i] = t.x; pqT[(m+1)*132 + i] = t.y;
        pqT[(m+2)*132 + i] = t.z; pqT[(m+3)*132 + i] = t.w;
        t = *reinterpret_cast<const float4*>(pkg + f);
        pkA[(m+0)*132 + i] = t.x; pkA[(m+1)*132 + i] = t.y;
        pkA[(m+2)*132 + i] = t.z; pkA[(m+3)*132 + i] = t.w;
    }
    const float* Sg = d_S + (size_t)(bh*NC + c) * (Mm*Dd);
    #pragma unroll
    for (int rep = 0; rep < 8; rep++) {
        int f = (rep*256 + tid) * 4;
        *reinterpret_cast<float4*>(vs + f) = *reinterpret_cast<const float4*>(vg + tok0*Dd + f);
        *reinterpret_cast<float4*>(Ss + f) = *reinterpret_cast<const float4*>(Sg + f);
    }
    if (tid < 128) zs[tid] = d_zz[(bh*NC + c)*Mm + tid];
    __syncthreads();

    const int tx = tid & 15, ty = tid >> 4;
    const int i0 = ty*8, j0 = tx*8;
    float acc[8][8];
    #pragma unroll
    for (int u = 0; u < 8; u++)
        #pragma unroll
        for (int w = 0; w < 8; w++) acc[u][w] = 0.f;

    for (int m = 0; m < 128; m++) {
        float a[8], b[8];
        float4 t;
        t = *reinterpret_cast<const float4*>(&pqT[m*132 + i0]);     a[0]=t.x;a[1]=t.y;a[2]=t.z;a[3]=t.w;
        t = *reinterpret_cast<const float4*>(&pqT[m*132 + i0 + 4]); a[4]=t.x;a[5]=t.y;a[6]=t.z;a[7]=t.w;
        t = *reinterpret_cast<const float4*>(&pkA[m*132 + j0]);     b[0]=t.x;b[1]=t.y;b[2]=t.z;b[3]=t.w;
        t = *reinterpret_cast<const float4*>(&pkA[m*132 + j0 + 4]); b[4]=t.x;b[5]=t.y;b[6]=t.z;b[7]=t.w;
        #pragma unroll
        for (int u = 0; u < 8; u++)
            #pragma unroll
            for (int w = 0; w < 8; w++) acc[u][w] = fmaf(a[u], b[w], acc[u][w]);
    }

    // causal mask (keep j <= i) + row sums
    #pragma unroll
    for (int u = 0; u < 8; u++) {
        float s = 0.f;
        #pragma unroll
        for (int w = 0; w < 8; w++) {
            if (j0 + w > i0 + u) acc[u][w] = 0.f;
            s += acc[u][w];
        }
        dp[(i0+u)*16 + tx] = s;
    }
    __syncthreads();  // all reads of pkT done

    // write A transposed over pkA: AT[j][i]
    #pragma unroll
    for (int w = 0; w < 8; w++) {
        float4 t0, t1;
        t0.x=acc[0][w]; t0.y=acc[1][w]; t0.z=acc[2][w]; t0.w=acc[3][w];
        t1.x=acc[4][w]; t1.y=acc[5][w]; t1.z=acc[6][w]; t1.w=acc[7][w];
        *reinterpret_cast<float4*>(&pkA[(j0+w)*132 + i0])     = t0;
        *reinterpret_cast<float4*>(&pkA[(j0+w)*132 + i0 + 4]) = t1;
    }
    __syncthreads();

    if (tid < 128) {
        float s = 0.f;
        #pragma unroll
        for (int t = 0; t < 16; t++) s += dp[tid*16 + t];
        float pz = 0.f;
        for (int m = 0; m < 128; m++) pz = fmaf(pqT[m*132 + tid], zs[m], pz);
        den[tid] = 1.f / (s + pz + EPS_DEN);
    }
    __syncthreads();

    const int d0 = tx*4;
    float o[8][4];
    #pragma unroll
    for (int u = 0; u < 8; u++)
        #pragma unroll
        for (int w = 0; w < 4; w++) o[u][w] = 0.f;

    for (int kk = 0; kk < 128; kk++) {   // intra: AT @ V
        float a[8];
        float4 t;
        t = *reinterpret_cast<const float4*>(&pkA[kk*132 + i0]);     a[0]=t.x;a[1]=t.y;a[2]=t.z;a[3]=t.w;
        t = *reinterpret_cast<const float4*>(&pkA[kk*132 + i0 + 4]); a[4]=t.x;a[5]=t.y;a[6]=t.z;a[7]=t.w;
        float4 b = *reinterpret_cast<const float4*>(&vs[kk*64 + d0]);
        #pragma unroll
        for (int u = 0; u < 8; u++) {
            o[u][0] = fmaf(a[u], b.x, o[u][0]);
            o[u][1] = fmaf(a[u], b.y, o[u][1]);
            o[u][2] = fmaf(a[u], b.z, o[u][2]);
            o[u][3] = fmaf(a[u], b.w, o[u][3]);
        }
    }
    for (int m = 0; m < 128; m++) {      // inter: phi_q @ S_prev
        float a[8];
        float4 t;
        t = *reinterpret_cast<const float4*>(&pqT[m*132 + i0]);     a[0]=t.x;a[1]=t.y;a[2]=t.z;a[3]=t.w;
        t = *reinterpret_cast<const float4*>(&pqT[m*132 + i0 + 4]); a[4]=t.x;a[5]=t.y;a[6]=t.z;a[7]=t.w;
        float4 b = *reinterpret_cast<const float4*>(&Ss[m*64 + d0]);
        #pragma unroll
        for (int u = 0; u < 8; u++) {
            o[u][0] = fmaf(a[u], b.x, o[u][0]);
            o[u][1] = fmaf(a[u], b.y, o[u][1]);
            o[u][2] = fmaf(a[u], b.z, o[u][2]);
            o[u][3] = fmaf(a[u], b.w, o[u][3]);
        }
    }

    float* og = outg + tok0 * Dd;
    #pragma unroll
    for (int u = 0; u < 8; u++) {
        float r = den[i0+u];
        float4 t;
        t.x = o[u][0]*r; t.y = o[u][1]*r; t.z = o[u][2]*r; t.w = o[u][3]*r;
        *reinterpret_cast<float4*>(og + (size_t)(i0+u)*Dd + d0) = t;
    }
}

// ---------------------------------------------------------------------------

extern "C" void kernel_launch(void* const* d_in, const int* in_sizes, int n_in,
                              void* d_out, int out_size) {
    const float* q  = (const float*)d_in[0];
    const float* k  = (const float*)d_in[1];
    const float* v  = (const float*)d_in[2];
    const float* om = (const float*)d_in[3];
    float* out = (float*)d_out;

    const int SM1 = 19072 * 4;   // 76288
    const int SM2 = 24576 * 4;   // 98304
    const int SM4 = 52480 * 4;   // 209920
    cudaFuncSetAttribute(k_proj,      cudaFuncAttributeMaxDynamicSharedMemorySize, SM1);
    cudaFuncSetAttribute(k_phik_sums, cudaFuncAttributeMaxDynamicSharedMemorySize, SM2);
    cudaFuncSetAttribute(k_out,       cudaFuncAttributeMaxDynamicSharedMemorySize, SM4);

    k_proj<<<2*NBT, 256, SM1>>>(q, k, om);
    k_gmax<<<1, 256>>>();
    k_phik_sums<<<NBT, 256, SM2>>>(v);
    k_scan<<<BH, 256>>>();
    k_out<<<NBT, 256, SM4>>>(v, out);
}

// round 2
// speedup vs baseline: 1.3265x; 1.3265x over previous
#include <cuda_runtime.h>

#define SCALE       0.35355339059327373f   // 64^(-1/4)
#define INV_SQRT_M  0.08838834764831843f   // 1/sqrt(128)
#define EPS_PHI     1e-4f
#define EPS_DEN     1e-6f

#define BH    64        // B*H = 4*16
#define Nn    4096
#define Dd    64
#define Mm    128
#define CH    128       // chunk length
#define NC    32        // chunks per head
#define NTOK  (BH*Nn)   // 262144
#define NBT   (NTOK/CH) // 2048 token-chunks

// Scratch (static __device__ — no allocations allowed)
__device__ float d_phiq[(size_t)NTOK*Mm];   // phi_q  [tok][m]
__device__ float d_phik[(size_t)NTOK*Mm];   // log-phi_k, then phi_k in place
__device__ float d_S[(size_t)BH*NC*Mm*Dd];  // chunk sums -> exclusive prefix states
__device__ float d_zz[BH*NC*Mm];            // chunk z sums -> exclusive prefix
__device__ float d_bmax[NBT];
__device__ float d_gmax;

// ---------------------------------------------------------------------------
// K1: proj = (x*scale) @ omega^T for q and k chunks.
//  q: finalize phi_q = exp(proj - rowmax(proj))/sqrt(M)+eps  (the -0.5||x||^2
//     cancels under the per-row max) and store.
//  k: store lp = proj - 0.5||x||^2, record block max for the global max.
// smem: xsT[64][132] omT[64][132] ss[128] red[2048]  (76288 B)
// ---------------------------------------------------------------------------
__global__ __launch_bounds__(256) void k_proj(const float* __restrict__ qg,
                                              const float* __restrict__ kg,
                                              const float* __restrict__ omg) {
    extern __shared__ float sm[];
    float* xsT = sm;               // [64][132]
    float* omT = sm + 64*132;      // [64][132]
    float* ss  = sm + 2*64*132;    // [128]
    float* red = ss + 128;         // [2048]

    const int bid = blockIdx.x;
    const bool isq = bid < NBT;
    const int tb  = isq ? bid : bid - NBT;
    const float* xg = (isq ? qg : kg) + (size_t)tb * CH * Dd;
    const int tid = threadIdx.x;

    // load x chunk [128][64] -> xsT[d][i] (scaled)
    #pragma unroll
    for (int rep = 0; rep < 8; rep++) {
        int idx = rep*256 + tid;
        int i  = idx >> 4;
        int d4 = (idx & 15) << 2;
        float4 t = *reinterpret_cast<const float4*>(xg + i*Dd + d4);
        xsT[(d4+0)*132 + i] = t.x * SCALE;
        xsT[(d4+1)*132 + i] = t.y * SCALE;
        xsT[(d4+2)*132 + i] = t.z * SCALE;
        xsT[(d4+3)*132 + i] = t.w * SCALE;
    }
    // omega [128][64] -> omT[d][m]
    #pragma unroll
    for (int rep = 0; rep < 8; rep++) {
        int idx = rep*256 + tid;
        int m  = idx >> 4;
        int d4 = (idx & 15) << 2;
        float4 t = *reinterpret_cast<const float4*>(omg + m*Dd + d4);
        omT[(d4+0)*132 + m] = t.x;
        omT[(d4+1)*132 + m] = t.y;
        omT[(d4+2)*132 + m] = t.z;
        omT[(d4+3)*132 + m] = t.w;
    }
    __syncthreads();
    if (tid < 128) {
        float s = 0.f;
        #pragma unroll
        for (int d = 0; d < 64; d++) { float vv = xsT[d*132 + tid]; s = fmaf(vv, vv, s); }
        ss[tid] = 0.5f * s;
    }
    __syncthreads();

    const int tx = tid & 15, ty = tid >> 4;
    const int i0 = ty*8, m0 = tx*8;
    float acc[8][8];
    #pragma unroll
    for (int u = 0; u < 8; u++)
        #pragma unroll
        for (int w = 0; w < 8; w++) acc[u][w] = 0.f;

    for (int d = 0; d < 64; d++) {
        float a[8], b[8];
        float4 t;
        t = *reinterpret_cast<const float4*>(&xsT[d*132 + i0]);     a[0]=t.x;a[1]=t.y;a[2]=t.z;a[3]=t.w;
        t = *reinterpret_cast<const float4*>(&xsT[d*132 + i0 + 4]); a[4]=t.x;a[5]=t.y;a[6]=t.z;a[7]=t.w;
        t = *reinterpret_cast<const float4*>(&omT[d*132 + m0]);     b[0]=t.x;b[1]=t.y;b[2]=t.z;b[3]=t.w;
        t = *reinterpret_cast<const float4*>(&omT[d*132 + m0 + 4]); b[4]=t.x;b[5]=t.y;b[6]=t.z;b[7]=t.w;
        #pragma unroll
        for (int u = 0; u < 8; u++)
            #pragma unroll
            for (int w = 0; w < 8; w++) acc[u][w] = fmaf(a[u], b[w], acc[u][w]);
    }

    const size_t tok0 = (size_t)tb * CH;
    if (isq) {
        #pragma unroll
        for (int u = 0; u < 8; u++) {
            float m = acc[u][0];
            #pragma unroll
            for (int w = 1; w < 8; w++) m = fmaxf(m, acc[u][w]);
            red[(i0+u)*16 + tx] = m;
        }
        __syncthreads();
        if (tid < 128) {
            float m = red[tid*16];
            #pragma unroll
            for (int t = 1; t < 16; t++) m = fmaxf(m, red[tid*16 + t]);
            ss[tid] = m;   // reuse as rowmax
        }
        __syncthreads();
        float* og = d_phiq + tok0 * Mm;
        #pragma unroll
        for (int u = 0; u < 8; u++) {
            float rm = ss[i0+u];
            float4 s0, s1;
            s0.x = __expf(acc[u][0]-rm)*INV_SQRT_M + EPS_PHI;
            s0.y = __expf(acc[u][1]-rm)*INV_SQRT_M + EPS_PHI;
            s0.z = __expf(acc[u][2]-rm)*INV_SQRT_M + EPS_PHI;
            s0.w = __expf(acc[u][3]-rm)*INV_SQRT_M + EPS_PHI;
            s1.x = __expf(acc[u][4]-rm)*INV_SQRT_M + EPS_PHI;
            s1.y = __expf(acc[u][5]-rm)*INV_SQRT_M + EPS_PHI;
            s1.z = __expf(acc[u][6]-rm)*INV_SQRT_M + EPS_PHI;
            s1.w = __expf(acc[u][7]-rm)*INV_SQRT_M + EPS_PHI;
            *reinterpret_cast<float4*>(og + (size_t)(i0+u)*Mm + m0)     = s0;
            *reinterpret_cast<float4*>(og + (size_t)(i0+u)*Mm + m0 + 4) = s1;
        }
    } else {
        float bm = -3.0e38f;
        float* og = d_phik + tok0 * Mm;
        #pragma unroll
        for (int u = 0; u < 8; u++) {
            float sr = ss[i0+u];
            #pragma unroll
            for (int w = 0; w < 8; w++) { acc[u][w] -= sr; bm = fmaxf(bm, acc[u][w]); }
            float4 s0, s1;
            s0.x=acc[u][0]; s0.y=acc[u][1]; s0.z=acc[u][2]; s0.w=acc[u][3];
            s1.x=acc[u][4]; s1.y=acc[u][5]; s1.z=acc[u][6]; s1.w=acc[u][7];
            *reinterpret_cast<float4*>(og + (size_t)(i0+u)*Mm + m0)     = s0;
            *reinterpret_cast<float4*>(og + (size_t)(i0+u)*Mm + m0 + 4) = s1;
        }
        red[tid] = bm;
        __syncthreads();
        for (int s = 128; s > 0; s >>= 1) {
            if (tid < s) red[tid] = fmaxf(red[tid], red[tid+s]);
            __syncthreads();
        }
        if (tid == 0) d_bmax[tb] = red[0];
    }
}

// K1b: reduce block maxima -> d_gmax
__global__ __launch_bounds__(256) void k_gmax() {
    __shared__ float red[256];
    const int tid = threadIdx.x;
    float m = -3.0e38f;
    for (int i = tid; i < NBT; i += 256) m = fmaxf(m, d_bmax[i]);
    red[tid] = m;
    __syncthreads();
    for (int s = 128; s > 0; s >>= 1) {
        if (tid < s) red[tid] = fmaxf(red[tid], red[tid+s]);
        __syncthreads();
    }
    if (tid == 0) d_gmax = red[0];
}

// ---------------------------------------------------------------------------
// K2: phi_k = exp(lp - gmax)/sqrt(M)+eps (written back); chunk Ssum = phi_k^T V,
// zsum = colsum(phi_k).  smem: phis[128][128] vs[128][64]  (98304 B)
// ---------------------------------------------------------------------------
__global__ __launch_bounds__(256) void k_phik_sums(const float* __restrict__ vg) {
    extern __shared__ float sm[];
    float* phis = sm;            // [128][128]
    float* vs   = sm + 128*128;  // [128][64]
    const int bid = blockIdx.x;
    const int bh = bid >> 5, c = bid & 31;
    const size_t tok0 = (size_t)bh * Nn + (size_t)c * CH;
    const int tid = threadIdx.x;
    const float gm = d_gmax;

    float* pk = d_phik + tok0 * Mm;
    #pragma unroll
    for (int rep = 0; rep < 16; rep++) {
        int idx = (rep*256 + tid) * 4;
        float4 t = *reinterpret_cast<const float4*>(pk + idx);
        t.x = __expf(t.x-gm)*INV_SQRT_M + EPS_PHI;
        t.y = __expf(t.y-gm)*INV_SQRT_M + EPS_PHI;
        t.z = __expf(t.z-gm)*INV_SQRT_M + EPS_PHI;
        t.w = __expf(t.w-gm)*INV_SQRT_M + EPS_PHI;
        *reinterpret_cast<float4*>(pk + idx)   = t;
        *reinterpret_cast<float4*>(phis + idx) = t;
    }
    #pragma unroll
    for (int rep = 0; rep < 8; rep++) {
        int idx = (rep*256 + tid) * 4;
        *reinterpret_cast<float4*>(vs + idx) =
            *reinterpret_cast<const float4*>(vg + tok0*Dd + idx);
    }
    __syncthreads();

    const int tx = tid & 15, ty = tid >> 4;
    const int m0 = ty*8, d0 = tx*4;
    float acc[8][4];
    float zacc[8];
    #pragma unroll
    for (int u = 0; u < 8; u++) {
        zacc[u] = 0.f;
        #pragma unroll
        for (int w = 0; w < 4; w++) acc[u][w] = 0.f;
    }
    for (int i = 0; i < 128; i++) {
        float a[8];
        float4 t;
        t = *reinterpret_cast<const float4*>(&phis[i*128 + m0]);     a[0]=t.x;a[1]=t.y;a[2]=t.z;a[3]=t.w;
        t = *reinterpret_cast<const float4*>(&phis[i*128 + m0 + 4]); a[4]=t.x;a[5]=t.y;a[6]=t.z;a[7]=t.w;
        float4 b = *reinterpret_cast<const float4*>(&vs[i*64 + d0]);
        #pragma unroll
        for (int u = 0; u < 8; u++) {
            acc[u][0] = fmaf(a[u], b.x, acc[u][0]);
            acc[u][1] = fmaf(a[u], b.y, acc[u][1]);
            acc[u][2] = fmaf(a[u], b.z, acc[u][2]);
            acc[u][3] = fmaf(a[u], b.w, acc[u][3]);
        }
        if (tx == 0) {
            #pragma unroll
            for (int u = 0; u < 8; u++) zacc[u] += a[u];
        }
    }
    float* Sg = d_S + (size_t)(bh*NC + c) * (Mm*Dd);
    #pragma unroll
    for (int u = 0; u < 8; u++) {
        float4 t; t.x=acc[u][0]; t.y=acc[u][1]; t.z=acc[u][2]; t.w=acc[u][3];
        *reinterpret_cast<float4*>(Sg + (m0+u)*Dd + d0) = t;
    }
    if (tx == 0) {
        float* zg = d_zz + (bh*NC + c) * Mm;
        #pragma unroll
        for (int u = 0; u < 8; u++) zg[m0+u] = zacc[u];
    }
}

// ---------------------------------------------------------------------------
// K3: exclusive prefix over the 32 chunks (per head), one chain per thread.
// Loads batched (MLP=32) before the register scan; stores independent.
// Grid: 2048 blocks for S (64 bh x 8192 elems) + 32 blocks for z (64 x 128).
// ---------------------------------------------------------------------------
__global__ __launch_bounds__(256) void k_scan() {
    const int gid = blockIdx.x * 256 + threadIdx.x;
    if (blockIdx.x < 2048) {
        const int bh = gid >> 13;           // / 8192
        const int e  = gid & 8191;
        const size_t p = (size_t)bh * NC * (Mm*Dd) + e;
        float v[NC];
        #pragma unroll
        for (int c = 0; c < NC; c++) v[c] = d_S[p + (size_t)c * (Mm*Dd)];
        float acc = 0.f;
        #pragma unroll
        for (int c = 0; c < NC; c++) {
            d_S[p + (size_t)c * (Mm*Dd)] = acc;
            acc += v[c];
        }
    } else {
        const int idx = gid - 2048*256;     // 0..8191
        const int bh = idx >> 7, m = idx & 127;
        const size_t p = (size_t)bh * NC * Mm + m;
        float v[NC];
        #pragma unroll
        for (int c = 0; c < NC; c++) v[c] = d_zz[p + c*Mm];
        float acc = 0.f;
        #pragma unroll
        for (int c = 0; c < NC; c++) {
            d_zz[p + c*Mm] = acc;
            acc += v[c];
        }
    }
}

// ---------------------------------------------------------------------------
// K4: A = phi_q phi_k^T (causal mask), out = (A V + phi_q S_prev) / den
// smem: pqT[128][132] pkA[128][132] vs[128][64] Ss[128][64] zs den dp (209920 B)
// ---------------------------------------------------------------------------
__global__ __launch_bounds__(256) void k_out(const float* __restrict__ vg,
                                             float* __restrict__ outg) {
    extern __shared__ float sm[];
    float* pqT = sm;                   // [128][132]  pqT[m][i]
    float* pkA = sm + 128*132;         // [128][132]  pkT[m][j] then AT[j][i]
    float* vs  = sm + 2*128*132;       // [128][64]
    float* Ss  = vs + 128*64;          // [128][64]
    float* zs  = Ss + 128*64;          // [128]
    float* den = zs + 128;             // [128]
    float* dp  = den + 128;            // [128*16]

    const int bid = blockIdx.x;
    const int bh = bid >> 5, c = bid & 31;
    const size_t tok0 = (size_t)bh * Nn + (size_t)c * CH;
    const int tid = threadIdx.x;

    const float* pqg = d_phiq + tok0 * Mm;
    const float* pkg = d_phik + tok0 * Mm;
    #pragma unroll
    for (int rep = 0; rep < 16; rep++) {
        int f = (rep*256 + tid) * 4;
        int i = f >> 7, m = f & 127;
        float4 t = *reinterpret_cast<const float4*>(pqg + f);
        pqT[(m+0)*132 + i] = t.x; pqT[(m+1)*132 + i] = t.y;
        pqT[(m+2)*132 + i] = t.z; pqT[(m+3)*132 + i] = t.w;
        t = *reinterpret_cast<const float4*>(pkg + f);
        pkA[(m+0)*132 + i] = t.x; pkA[(m+1)*132 + i] = t.y;
        pkA[(m+2)*132 + i] = t.z; pkA[(m+3)*132 + i] = t.w;
    }
    const float* Sg = d_S + (size_t)(bh*NC + c) * (Mm*Dd);
    #pragma unroll
    for (int rep = 0; rep < 8; rep++) {
        int f = (rep*256 + tid) * 4;
        *reinterpret_cast<float4*>(vs + f) = *reinterpret_cast<const float4*>(vg + tok0*Dd + f);
        *reinterpret_cast<float4*>(Ss + f) = *reinterpret_cast<const float4*>(Sg + f);
    }
    if (tid < 128) zs[tid] = d_zz[(bh*NC + c)*Mm + tid];
    __syncthreads();

    const int tx = tid & 15, ty = tid >> 4;
    const int i0 = ty*8, j0 = tx*8;
    float acc[8][8];
    #pragma unroll
    for (int u = 0; u < 8; u++)
        #pragma unroll
        for (int w = 0; w < 8; w++) acc[u][w] = 0.f;

    for (int m = 0; m < 128; m++) {
        float a[8], b[8];
        float4 t;
        t = *reinterpret_cast<const float4*>(&pqT[m*132 + i0]);     a[0]=t.x;a[1]=t.y;a[2]=t.z;a[3]=t.w;
        t = *reinterpret_cast<const float4*>(&pqT[m*132 + i0 + 4]); a[4]=t.x;a[5]=t.y;a[6]=t.z;a[7]=t.w;
        t = *reinterpret_cast<const float4*>(&pkA[m*132 + j0]);     b[0]=t.x;b[1]=t.y;b[2]=t.z;b[3]=t.w;
        t = *reinterpret_cast<const float4*>(&pkA[m*132 + j0 + 4]); b[4]=t.x;b[5]=t.y;b[6]=t.z;b[7]=t.w;
        #pragma unroll
        for (int u = 0; u < 8; u++)
            #pragma unroll
            for (int w = 0; w < 8; w++) acc[u][w] = fmaf(a[u], b[w], acc[u][w]);
    }

    // causal mask (keep j <= i) + row sums
    #pragma unroll
    for (int u = 0; u < 8; u++) {
        float s = 0.f;
        #pragma unroll
        for (int w = 0; w < 8; w++) {
            if (j0 + w > i0 + u) acc[u][w] = 0.f;
            s += acc[u][w];
        }
        dp[(i0+u)*16 + tx] = s;
    }
    __syncthreads();  // all reads of pkT done

    // write A transposed over pkA: AT[j][i]
    #pragma unroll
    for (int w = 0; w < 8; w++) {
        float4 t0, t1;
        t0.x=acc[0][w]; t0.y=acc[1][w]; t0.z=acc[2][w]; t0.w=acc[3][w];
        t1.x=acc[4][w]; t1.y=acc[5][w]; t1.z=acc[6][w]; t1.w=acc[7][w];
        *reinterpret_cast<float4*>(&pkA[(j0+w)*132 + i0])     = t0;
        *reinterpret_cast<float4*>(&pkA[(j0+w)*132 + i0 + 4]) = t1;
    }
    __syncthreads();

    if (tid < 128) {
        float s = 0.f;
        #pragma unroll
        for (int t = 0; t < 16; t++) s += dp[tid*16 + t];
        float pz = 0.f;
        for (int m = 0; m < 128; m++) pz = fmaf(pqT[m*132 + tid], zs[m], pz);
        den[tid] = 1.f / (s + pz + EPS_DEN);
    }
    __syncthreads();

    const int d0 = tx*4;
    float o[8][4];
    #pragma unroll
    for (int u = 0; u < 8; u++)
        #pragma unroll
        for (int w = 0; w < 4; w++) o[u][w] = 0.f;

    for (int kk = 0; kk < 128; kk++) {   // intra: AT @ V
        float a[8];
        float4 t;
        t = *reinterpret_cast<const float4*>(&pkA[kk*132 + i0]);     a[0]=t.x;a[1]=t.y;a[2]=t.z;a[3]=t.w;
        t = *reinterpret_cast<const float4*>(&pkA[kk*132 + i0 + 4]); a[4]=t.x;a[5]=t.y;a[6]=t.z;a[7]=t.w;
        float4 b = *reinterpret_cast<const float4*>(&vs[kk*64 + d0]);
        #pragma unroll
        for (int u = 0; u < 8; u++) {
            o[u][0] = fmaf(a[u], b.x, o[u][0]);
            o[u][1] = fmaf(a[u], b.y, o[u][1]);
            o[u][2] = fmaf(a[u], b.z, o[u][2]);
            o[u][3] = fmaf(a[u], b.w, o[u][3]);
        }
    }
    for (int m = 0; m < 128; m++) {      // inter: phi_q @ S_prev
        float a[8];
        float4 t;
        t = *reinterpret_cast<const float4*>(&pqT[m*132 + i0]);     a[0]=t.x;a[1]=t.y;a[2]=t.z;a[3]=t.w;
        t = *reinterpret_cast<const float4*>(&pqT[m*132 + i0 + 4]); a[4]=t.x;a[5]=t.y;a[6]=t.z;a[7]=t.w;
        float4 b = *reinterpret_cast<const float4*>(&Ss[m*64 + d0]);
        #pragma unroll
        for (int u = 0; u < 8; u++) {
            o[u][0] = fmaf(a[u], b.x, o[u][0]);
            o[u][1] = fmaf(a[u], b.y, o[u][1]);
            o[u][2] = fmaf(a[u], b.z, o[u][2]);
            o[u][3] = fmaf(a[u], b.w, o[u][3]);
        }
    }

    float* og = outg + tok0 * Dd;
    #pragma unroll
    for (int u = 0; u < 8; u++) {
        float r = den[i0+u];
        float4 t;
        t.x = o[u][0]*r; t.y = o[u][1]*r; t.z = o[u][2]*r; t.w = o[u][3]*r;
        *reinterpret_cast<float4*>(og + (size_t)(i0+u)*Dd + d0) = t;
    }
}

// ---------------------------------------------------------------------------

extern "C" void kernel_launch(void* const* d_in, const int* in_sizes, int n_in,
                              void* d_out, int out_size) {
    const float* q  = (const float*)d_in[0];
    const float* k  = (const float*)d_in[1];
    const float* v  = (const float*)d_in[2];
    const float* om = (const float*)d_in[3];
    float* out = (float*)d_out;

    const int SM1 = 19072 * 4;   // 76288
    const int SM2 = 24576 * 4;   // 98304
    const int SM4 = 52480 * 4;   // 209920
    cudaFuncSetAttribute(k_proj,      cudaFuncAttributeMaxDynamicSharedMemorySize, SM1);
    cudaFuncSetAttribute(k_phik_sums, cudaFuncAttributeMaxDynamicSharedMemorySize, SM2);
    cudaFuncSetAttribute(k_out,       cudaFuncAttributeMaxDynamicSharedMemorySize, SM4);

    k_proj<<<2*NBT, 256, SM1>>>(q, k, om);
    k_gmax<<<1, 256>>>();
    k_phik_sums<<<NBT, 256, SM2>>>(v);
    k_scan<<<2048 + 32, 256>>>();
    k_out<<<NBT, 256, SM4>>>(v, out);
}

// round 3
// speedup vs baseline: 1.4373x; 1.0835x over previous
#include <cuda_runtime.h>

#define SCALE       0.35355339059327373f   // 64^(-1/4)
#define INV_SQRT_M  0.08838834764831843f   // 1/sqrt(128)
#define EPS_PHI     1e-4f
#define EPS_DEN     1e-6f

#define BH    64        // B*H = 4*16
#define Nn    4096
#define Dd    64
#define Mm    128
#define CH    128       // chunk length
#define NC    32        // chunks per head
#define NTOK  (BH*Nn)   // 262144
#define NBT   (NTOK/CH) // 2048 token-chunks

typedef unsigned long long u64;

// packed fp32x2 helpers (SASS FFMA2 — only reachable via PTX)
__device__ __forceinline__ u64 pk2(float x, float y) {
    u64 r; asm("mov.b64 %0, {%1,%2};" : "=l"(r) : "f"(x), "f"(y)); return r;
}
__device__ __forceinline__ void upk2(u64 p, float& x, float& y) {
    asm("mov.b64 {%0,%1}, %2;" : "=f"(x), "=f"(y) : "l"(p));
}
__device__ __forceinline__ u64 ffma2(u64 a, u64 b, u64 c) {
    u64 d; asm("fma.rn.f32x2 %0, %1, %2, %3;" : "=l"(d) : "l"(a), "l"(b), "l"(c)); return d;
}

// Scratch (static __device__ — no allocations allowed)
__device__ float d_phiq[(size_t)NTOK*Mm];   // phi_q  [tok][m]
__device__ float d_phik[(size_t)NTOK*Mm];   // log-phi_k, then phi_k in place
__device__ float d_S[(size_t)BH*NC*Mm*Dd];  // chunk sums -> exclusive prefix states
__device__ float d_zz[BH*NC*Mm];            // chunk z sums -> exclusive prefix
__device__ float d_bmax[NBT];
__device__ float d_gmax;

// ---------------------------------------------------------------------------
// K1: proj = (x*scale) @ omega^T for q and k chunks.
// ---------------------------------------------------------------------------
__global__ __launch_bounds__(256) void k_proj(const float* __restrict__ qg,
                                              const float* __restrict__ kg,
                                              const float* __restrict__ omg) {
    extern __shared__ float sm[];
    float* xsT = sm;               // [64][132]
    float* omT = sm + 64*132;      // [64][132]
    float* ss  = sm + 2*64*132;    // [128]
    float* red = ss + 128;         // [2048]

    const int bid = blockIdx.x;
    const bool isq = bid < NBT;
    const int tb  = isq ? bid : bid - NBT;
    const float* xg = (isq ? qg : kg) + (size_t)tb * CH * Dd;
    const int tid = threadIdx.x;

    #pragma unroll
    for (int rep = 0; rep < 8; rep++) {
        int idx = rep*256 + tid;
        int i  = idx >> 4;
        int d4 = (idx & 15) << 2;
        float4 t = *reinterpret_cast<const float4*>(xg + i*Dd + d4);
        xsT[(d4+0)*132 + i] = t.x * SCALE;
        xsT[(d4+1)*132 + i] = t.y * SCALE;
        xsT[(d4+2)*132 + i] = t.z * SCALE;
        xsT[(d4+3)*132 + i] = t.w * SCALE;
    }
    #pragma unroll
    for (int rep = 0; rep < 8; rep++) {
        int idx = rep*256 + tid;
        int m  = idx >> 4;
        int d4 = (idx & 15) << 2;
        float4 t = *reinterpret_cast<const float4*>(omg + m*Dd + d4);
        omT[(d4+0)*132 + m] = t.x;
        omT[(d4+1)*132 + m] = t.y;
        omT[(d4+2)*132 + m] = t.z;
        omT[(d4+3)*132 + m] = t.w;
    }
    __syncthreads();
    if (tid < 128) {
        float s = 0.f;
        #pragma unroll
        for (int d = 0; d < 64; d++) { float vv = xsT[d*132 + tid]; s = fmaf(vv, vv, s); }
        ss[tid] = 0.5f * s;
    }
    __syncthreads();

    const int tx = tid & 15, ty = tid >> 4;
    const int i0 = ty*8, m0 = tx*8;
    u64 acc2[8][4];
    #pragma unroll
    for (int u = 0; u < 8; u++)
        #pragma unroll
        for (int w = 0; w < 4; w++) acc2[u][w] = 0ull;

    for (int d = 0; d < 64; d++) {
        float a[8];
        float4 t;
        t = *reinterpret_cast<const float4*>(&xsT[d*132 + i0]);     a[0]=t.x;a[1]=t.y;a[2]=t.z;a[3]=t.w;
        t = *reinterpret_cast<const float4*>(&xsT[d*132 + i0 + 4]); a[4]=t.x;a[5]=t.y;a[6]=t.z;a[7]=t.w;
        u64 a2[8];
        #pragma unroll
        for (int u = 0; u < 8; u++) a2[u] = pk2(a[u], a[u]);
        ulonglong2 bb0 = *reinterpret_cast<const ulonglong2*>(&omT[d*132 + m0]);
        ulonglong2 bb1 = *reinterpret_cast<const ulonglong2*>(&omT[d*132 + m0 + 4]);
        u64 b2[4] = {bb0.x, bb0.y, bb1.x, bb1.y};
        #pragma unroll
        for (int u = 0; u < 8; u++)
            #pragma unroll
            for (int w = 0; w < 4; w++) acc2[u][w] = ffma2(a2[u], b2[w], acc2[u][w]);
    }
    float acc[8][8];
    #pragma unroll
    for (int u = 0; u < 8; u++)
        #pragma unroll
        for (int w = 0; w < 4; w++) upk2(acc2[u][w], acc[u][2*w], acc[u][2*w+1]);

    const size_t tok0 = (size_t)tb * CH;
    if (isq) {
        #pragma unroll
        for (int u = 0; u < 8; u++) {
            float m = acc[u][0];
            #pragma unroll
            for (int w = 1; w < 8; w++) m = fmaxf(m, acc[u][w]);
            red[(i0+u)*16 + tx] = m;
        }
        __syncthreads();
        if (tid < 128) {
            float m = red[tid*16];
            #pragma unroll
            for (int t = 1; t < 16; t++) m = fmaxf(m, red[tid*16 + t]);
            ss[tid] = m;   // reuse as rowmax
        }
        __syncthreads();
        float* og = d_phiq + tok0 * Mm;
        #pragma unroll
        for (int u = 0; u < 8; u++) {
            float rm = ss[i0+u];
            float4 s0, s1;
            s0.x = __expf(acc[u][0]-rm)*INV_SQRT_M + EPS_PHI;
            s0.y = __expf(acc[u][1]-rm)*INV_SQRT_M + EPS_PHI;
            s0.z = __expf(acc[u][2]-rm)*INV_SQRT_M + EPS_PHI;
            s0.w = __expf(acc[u][3]-rm)*INV_SQRT_M + EPS_PHI;
            s1.x = __expf(acc[u][4]-rm)*INV_SQRT_M + EPS_PHI;
            s1.y = __expf(acc[u][5]-rm)*INV_SQRT_M + EPS_PHI;
            s1.z = __expf(acc[u][6]-rm)*INV_SQRT_M + EPS_PHI;
            s1.w = __expf(acc[u][7]-rm)*INV_SQRT_M + EPS_PHI;
            *reinterpret_cast<float4*>(og + (size_t)(i0+u)*Mm + m0)     = s0;
            *reinterpret_cast<float4*>(og + (size_t)(i0+u)*Mm + m0 + 4) = s1;
        }
    } else {
        float bm = -3.0e38f;
        float* og = d_phik + tok0 * Mm;
        #pragma unroll
        for (int u = 0; u < 8; u++) {
            float sr = ss[i0+u];
            #pragma unroll
            for (int w = 0; w < 8; w++) { acc[u][w] -= sr; bm = fmaxf(bm, acc[u][w]); }
            float4 s0, s1;
            s0.x=acc[u][0]; s0.y=acc[u][1]; s0.z=acc[u][2]; s0.w=acc[u][3];
            s1.x=acc[u][4]; s1.y=acc[u][5]; s1.z=acc[u][6]; s1.w=acc[u][7];
            *reinterpret_cast<float4*>(og + (size_t)(i0+u)*Mm + m0)     = s0;
            *reinterpret_cast<float4*>(og + (size_t)(i0+u)*Mm + m0 + 4) = s1;
        }
        red[tid] = bm;
        __syncthreads();
        for (int s = 128; s > 0; s >>= 1) {
            if (tid < s) red[tid] = fmaxf(red[tid], red[tid+s]);
            __syncthreads();
        }
        if (tid == 0) d_bmax[tb] = red[0];
    }
}

// K1b: reduce block maxima -> d_gmax
__global__ __launch_bounds__(256) void k_gmax() {
    __shared__ float red[256];
    const int tid = threadIdx.x;
    float m = -3.0e38f;
    for (int i = tid; i < NBT; i += 256) m = fmaxf(m, d_bmax[i]);
    red[tid] = m;
    __syncthreads();
    for (int s = 128; s > 0; s >>= 1) {
        if (tid < s) red[tid] = fmaxf(red[tid], red[tid+s]);
        __syncthreads();
    }
    if (tid == 0) d_gmax = red[0];
}

// ---------------------------------------------------------------------------
// K2: phi_k = exp(lp - gmax)/sqrt(M)+eps (written back); chunk Ssum = phi_k^T V,
// zsum = colsum(phi_k).
// ---------------------------------------------------------------------------
__global__ __launch_bounds__(256) void k_phik_sums(const float* __restrict__ vg) {
    extern __shared__ float sm[];
    float* phis = sm;            // [128][128]
    float* vs   = sm + 128*128;  // [128][64]
    const int bid = blockIdx.x;
    const int bh = bid >> 5, c = bid & 31;
    const size_t tok0 = (size_t)bh * Nn + (size_t)c * CH;
    const int tid = threadIdx.x;
    const float gm = d_gmax;

    float* pk = d_phik + tok0 * Mm;
    #pragma unroll
    for (int rep = 0; rep < 16; rep++) {
        int idx = (rep*256 + tid) * 4;
        float4 t = *reinterpret_cast<const float4*>(pk + idx);
        t.x = __expf(t.x-gm)*INV_SQRT_M + EPS_PHI;
        t.y = __expf(t.y-gm)*INV_SQRT_M + EPS_PHI;
        t.z = __expf(t.z-gm)*INV_SQRT_M + EPS_PHI;
        t.w = __expf(t.w-gm)*INV_SQRT_M + EPS_PHI;
        *reinterpret_cast<float4*>(pk + idx)   = t;
        *reinterpret_cast<float4*>(phis + idx) = t;
    }
    #pragma unroll
    for (int rep = 0; rep < 8; rep++) {
        int idx = (rep*256 + tid) * 4;
        *reinterpret_cast<float4*>(vs + idx) =
            *reinterpret_cast<const float4*>(vg + tok0*Dd + idx);
    }
    __syncthreads();

    const int tx = tid & 15, ty = tid >> 4;
    const int m0 = ty*8, d0 = tx*4;
    u64 acc2[8][2];
    float zacc[8];
    #pragma unroll
    for (int u = 0; u < 8; u++) {
        zacc[u] = 0.f;
        acc2[u][0] = 0ull; acc2[u][1] = 0ull;
    }
    for (int i = 0; i < 128; i++) {
        float a[8];
        float4 t;
        t = *reinterpret_cast<const float4*>(&phis[i*128 + m0]);     a[0]=t.x;a[1]=t.y;a[2]=t.z;a[3]=t.w;
        t = *reinterpret_cast<const float4*>(&phis[i*128 + m0 + 4]); a[4]=t.x;a[5]=t.y;a[6]=t.z;a[7]=t.w;
        u64 a2[8];
        #pragma unroll
        for (int u = 0; u < 8; u++) a2[u] = pk2(a[u], a[u]);
        ulonglong2 bb = *reinterpret_cast<const ulonglong2*>(&vs[i*64 + d0]);
        #pragma unroll
        for (int u = 0; u < 8; u++) {
            acc2[u][0] = ffma2(a2[u], bb.x, acc2[u][0]);
            acc2[u][1] = ffma2(a2[u], bb.y, acc2[u][1]);
        }
        if (tx == 0) {
            #pragma unroll
            for (int u = 0; u < 8; u++) zacc[u] += a[u];
        }
    }
    float* Sg = d_S + (size_t)(bh*NC + c) * (Mm*Dd);
    #pragma unroll
    for (int u = 0; u < 8; u++) {
        float4 t;
        upk2(acc2[u][0], t.x, t.y);
        upk2(acc2[u][1], t.z, t.w);
        *reinterpret_cast<float4*>(Sg + (m0+u)*Dd + d0) = t;
    }
    if (tx == 0) {
        float* zg = d_zz + (bh*NC + c) * Mm;
        #pragma unroll
        for (int u = 0; u < 8; u++) zg[m0+u] = zacc[u];
    }
}

// ---------------------------------------------------------------------------
// K3: exclusive prefix over the 32 chunks (per head), one chain per thread.
// ---------------------------------------------------------------------------
__global__ __launch_bounds__(256) void k_scan() {
    const int gid = blockIdx.x * 256 + threadIdx.x;
    if (blockIdx.x < 2048) {
        const int bh = gid >> 13;           // / 8192
        const int e  = gid & 8191;
        const size_t p = (size_t)bh * NC * (Mm*Dd) + e;
        float v[NC];
        #pragma unroll
        for (int c = 0; c < NC; c++) v[c] = d_S[p + (size_t)c * (Mm*Dd)];
        float acc = 0.f;
        #pragma unroll
        for (int c = 0; c < NC; c++) {
            d_S[p + (size_t)c * (Mm*Dd)] = acc;
            acc += v[c];
        }
    } else {
        const int idx = gid - 2048*256;     // 0..8191
        const int bh = idx >> 7, m = idx & 127;
        const size_t p = (size_t)bh * NC * Mm + m;
        float v[NC];
        #pragma unroll
        for (int c = 0; c < NC; c++) v[c] = d_zz[p + c*Mm];
        float acc = 0.f;
        #pragma unroll
        for (int c = 0; c < NC; c++) {
            d_zz[p + c*Mm] = acc;
            acc += v[c];
        }
    }
}

// ---------------------------------------------------------------------------
// K4: A = phi_q phi_k^T (causal mask), out = (A V + phi_q S_prev) / den
// ---------------------------------------------------------------------------
__global__ __launch_bounds__(256) void k_out(const float* __restrict__ vg,
                                             float* __restrict__ outg) {
    extern __shared__ float sm[];
    float* pqT = sm;                   // [128][132]  pqT[m][i]
    float* pkA = sm + 128*132;         // [128][132]  pkT[m][j] then AT[j][i]
    float* vs  = sm + 2*128*132;       // [128][64]
    float* Ss  = vs + 128*64;          // [128][64]
    float* zs  = Ss + 128*64;          // [128]
    float* den = zs + 128;             // [128]
    float* dp  = den + 128;            // [128*16]

    const int bid = blockIdx.x;
    const int bh = bid >> 5, c = bid & 31;
    const size_t tok0 = (size_t)bh * Nn + (size_t)c * CH;
    const int tid = threadIdx.x;

    const float* pqg = d_phiq + tok0 * Mm;
    const float* pkg = d_phik + tok0 * Mm;
    #pragma unroll
    for (int rep = 0; rep < 16; rep++) {
        int f = (rep*256 + tid) * 4;
        int i = f >> 7, m = f & 127;
        float4 t = *reinterpret_cast<const float4*>(pqg + f);
        pqT[(m+0)*132 + i] = t.x; pqT[(m+1)*132 + i] = t.y;
        pqT[(m+2)*132 + i] = t.z; pqT[(m+3)*132 + i] = t.w;
        t = *reinterpret_cast<const float4*>(pkg + f);
        pkA[(m+0)*132 + i] = t.x; pkA[(m+1)*132 + i] = t.y;
        pkA[(m+2)*132 + i] = t.z; pkA[(m+3)*132 + i] = t.w;
    }
    const float* Sg = d_S + (size_t)(bh*NC + c) * (Mm*Dd);
    #pragma unroll
    for (int rep = 0; rep < 8; rep++) {
        int f = (rep*256 + tid) * 4;
        *reinterpret_cast<float4*>(vs + f) = *reinterpret_cast<const float4*>(vg + tok0*Dd + f);
        *reinterpret_cast<float4*>(Ss + f) = *reinterpret_cast<const float4*>(Sg + f);
    }
    if (tid < 128) zs[tid] = d_zz[(bh*NC + c)*Mm + tid];
    __syncthreads();

    const int tx = tid & 15, ty = tid >> 4;
    const int i0 = ty*8, j0 = tx*8;
    u64 acc2[8][4];
    #pragma unroll
    for (int u = 0; u < 8; u++)
        #pragma unroll
        for (int w = 0; w < 4; w++) acc2[u][w] = 0ull;

    for (int m = 0; m < 128; m++) {
        float a[8];
        float4 t;
        t = *reinterpret_cast<const float4*>(&pqT[m*132 + i0]);     a[0]=t.x;a[1]=t.y;a[2]=t.z;a[3]=t.w;
        t = *reinterpret_cast<const float4*>(&pqT[m*132 + i0 + 4]); a[4]=t.x;a[5]=t.y;a[6]=t.z;a[7]=t.w;
        u64 a2[8];
        #pragma unroll
        for (int u = 0; u < 8; u++) a2[u] = pk2(a[u], a[u]);
        ulonglong2 bb0 = *reinterpret_cast<const ulonglong2*>(&pkA[m*132 + j0]);
        ulonglong2 bb1 = *reinterpret_cast<const ulonglong2*>(&pkA[m*132 + j0 + 4]);
        u64 b2[4] = {bb0.x, bb0.y, bb1.x, bb1.y};
        #pragma unroll
        for (int u = 0; u < 8; u++)
            #pragma unroll
            for (int w = 0; w < 4; w++) acc2[u][w] = ffma2(a2[u], b2[w], acc2[u][w]);
    }
    float acc[8][8];
    #pragma unroll
    for (int u = 0; u < 8; u++)
        #pragma unroll
        for (int w = 0; w < 4; w++) upk2(acc2[u][w], acc[u][2*w], acc[u][2*w+1]);

    // causal mask (keep j <= i) + row sums
    #pragma unroll
    for (int u = 0; u < 8; u++) {
        float s = 0.f;
        #pragma unroll
        for (int w = 0; w < 8; w++) {
            if (j0 + w > i0 + u) acc[u][w] = 0.f;
            s += acc[u][w];
        }
        dp[(i0+u)*16 + tx] = s;
    }
    __syncthreads();  // all reads of pkT done

    // write A transposed over pkA: AT[j][i]
    #pragma unroll
    for (int w = 0; w < 8; w++) {
        float4 t0, t1;
        t0.x=acc[0][w]; t0.y=acc[1][w]; t0.z=acc[2][w]; t0.w=acc[3][w];
        t1.x=acc[4][w]; t1.y=acc[5][w]; t1.z=acc[6][w]; t1.w=acc[7][w];
        *reinterpret_cast<float4*>(&pkA[(j0+w)*132 + i0])     = t0;
        *reinterpret_cast<float4*>(&pkA[(j0+w)*132 + i0 + 4]) = t1;
    }
    __syncthreads();

    if (tid < 128) {
        float s = 0.f;
        #pragma unroll
        for (int t = 0; t < 16; t++) s += dp[tid*16 + t];
        float pz = 0.f;
        for (int m = 0; m < 128; m++) pz = fmaf(pqT[m*132 + tid], zs[m], pz);
        den[tid] = 1.f / (s + pz + EPS_DEN);
    }
    __syncthreads();

    const int d0 = tx*4;
    u64 o2[8][2];
    #pragma unroll
    for (int u = 0; u < 8; u++) { o2[u][0] = 0ull; o2[u][1] = 0ull; }

    // intra: AT @ V — kk > i0+7 rows of AT are zero (masked), skip them
    const int kmax = i0 + 8;
    #pragma unroll 4
    for (int kk = 0; kk < kmax; kk++) {
        float a[8];
        float4 t;
        t = *reinterpret_cast<const float4*>(&pkA[kk*132 + i0]);     a[0]=t.x;a[1]=t.y;a[2]=t.z;a[3]=t.w;
        t = *reinterpret_cast<const float4*>(&pkA[kk*132 + i0 + 4]); a[4]=t.x;a[5]=t.y;a[6]=t.z;a[7]=t.w;
        ulonglong2 bb = *reinterpret_cast<const ulonglong2*>(&vs[kk*64 + d0]);
        #pragma unroll
        for (int u = 0; u < 8; u++) {
            u64 a2 = pk2(a[u], a[u]);
            o2[u][0] = ffma2(a2, bb.x, o2[u][0]);
            o2[u][1] = ffma2(a2, bb.y, o2[u][1]);
        }
    }
    // inter: phi_q @ S_prev
    for (int m = 0; m < 128; m++) {
        float a[8];
        float4 t;
        t = *reinterpret_cast<const float4*>(&pqT[m*132 + i0]);     a[0]=t.x;a[1]=t.y;a[2]=t.z;a[3]=t.w;
        t = *reinterpret_cast<const float4*>(&pqT[m*132 + i0 + 4]); a[4]=t.x;a[5]=t.y;a[6]=t.z;a[7]=t.w;
        ulonglong2 bb = *reinterpret_cast<const ulonglong2*>(&Ss[m*64 + d0]);
        #pragma unroll
        for (int u = 0; u < 8; u++) {
            u64 a2 = pk2(a[u], a[u]);
            o2[u][0] = ffma2(a2, bb.x, o2[u][0]);
            o2[u][1] = ffma2(a2, bb.y, o2[u][1]);
        }
    }

    float* og = outg + tok0 * Dd;
    #pragma unroll
    for (int u = 0; u < 8; u++) {
        float r = den[i0+u];
        float4 t;
        upk2(o2[u][0], t.x, t.y);
        upk2(o2[u][1], t.z, t.w);
        t.x *= r; t.y *= r; t.z *= r; t.w *= r;
        *reinterpret_cast<float4*>(og + (size_t)(i0+u)*Dd + d0) = t;
    }
}

// ---------------------------------------------------------------------------

extern "C" void kernel_launch(void* const* d_in, const int* in_sizes, int n_in,
                              void* d_out, int out_size) {
    const float* q  = (const float*)d_in[0];
    const float* k  = (const float*)d_in[1];
    const float* v  = (const float*)d_in[2];
    const float* om = (const float*)d_in[3];
    float* out = (float*)d_out;

    const int SM1 = 19072 * 4;   // 76288
    const int SM2 = 24576 * 4;   // 98304
    const int SM4 = 52480 * 4;   // 209920
    cudaFuncSetAttribute(k_proj,      cudaFuncAttributeMaxDynamicSharedMemorySize, SM1);
    cudaFuncSetAttribute(k_phik_sums, cudaFuncAttributeMaxDynamicSharedMemorySize, SM2);
    cudaFuncSetAttribute(k_out,       cudaFuncAttributeMaxDynamicSharedMemorySize, SM4);

    k_proj<<<2*NBT, 256, SM1>>>(q, k, om);
    k_gmax<<<1, 256>>>();
    k_phik_sums<<<NBT, 256, SM2>>>(v);
    k_scan<<<2048 + 32, 256>>>();
    k_out<<<NBT, 256, SM4>>>(v, out);
}

// round 5
// speedup vs baseline: 1.9407x; 1.3502x over previous
#include <cuda_runtime.h>
#include <cuda_bf16.h>
#include <cstdint>

#define SCALE       0.35355339059327373f   // 64^(-1/4)
#define INV_SQRT_M  0.08838834764831843f   // 1/sqrt(128)
#define EPS_PHI     1e-4f
#define EPS_DEN     1e-6f

#define BH    64        // B*H = 4*16
#define Nn    4096
#define Dd    64
#define Mm    128
#define CH    128       // chunk length
#define NC    32        // chunks per head
#define NTOK  (BH*Nn)   // 262144
#define NBT   (NTOK/CH) // 2048 token-chunks

typedef unsigned long long u64;
typedef unsigned int u32;

// ---------------- packed fp32x2 (K1/K2) ----------------
__device__ __forceinline__ u64 pk2(float x, float y) {
    u64 r; asm("mov.b64 %0, {%1,%2};" : "=l"(r) : "f"(x), "f"(y)); return r;
}
__device__ __forceinline__ void upk2(u64 p, float& x, float& y) {
    asm("mov.b64 {%0,%1}, %2;" : "=f"(x), "=f"(y) : "l"(p));
}
__device__ __forceinline__ u64 ffma2(u64 a, u64 b, u64 c) {
    u64 d; asm("fma.rn.f32x2 %0, %1, %2, %3;" : "=l"(d) : "l"(a), "l"(b), "l"(c)); return d;
}

// ---------------- warp MMA helpers (compute_103-portable) ----------------
__device__ __forceinline__ u32 s2u(const void* p) {
    u32 a; asm("{ .reg .u64 t; cvta.to.shared.u64 t, %1; cvt.u32.u64 %0, t; }"
               : "=r"(a) : "l"(p));
    return a;
}
__device__ __forceinline__ void ldsm4(u32& r0, u32& r1, u32& r2, u32& r3, u32 addr) {
    asm volatile("ldmatrix.sync.aligned.m8n8.x4.shared.b16 {%0,%1,%2,%3}, [%4];"
                 : "=r"(r0), "=r"(r1), "=r"(r2), "=r"(r3) : "r"(addr));
}
__device__ __forceinline__ void ldsm2(u32& r0, u32& r1, u32 addr) {
    asm volatile("ldmatrix.sync.aligned.m8n8.x2.shared.b16 {%0,%1}, [%2];"
                 : "=r"(r0), "=r"(r1) : "r"(addr));
}
__device__ __forceinline__ void mma16816(float* d, u32 a0, u32 a1, u32 a2, u32 a3,
                                         u32 b0, u32 b1) {
    asm volatile("mma.sync.aligned.m16n8k16.row.col.f32.bf16.bf16.f32 "
                 "{%0,%1,%2,%3}, {%4,%5,%6,%7}, {%8,%9}, {%0,%1,%2,%3};"
                 : "+f"(d[0]), "+f"(d[1]), "+f"(d[2]), "+f"(d[3])
                 : "r"(a0), "r"(a1), "r"(a2), "r"(a3), "r"(b0), "r"(b1));
}

// bf16 split
__device__ __forceinline__ unsigned short bf16h(float x) {
    unsigned short u; asm("cvt.rn.bf16.f32 %0, %1;" : "=h"(u) : "f"(x)); return u;
}
__device__ __forceinline__ float bf2f(unsigned short u) {
    float f; asm("cvt.f32.bf16 %0, %1;" : "=f"(f) : "h"(u)); return f;
}
__device__ __forceinline__ void split2(float x, unsigned short& h, unsigned short& l) {
    h = bf16h(x); l = bf16h(x - bf2f(h));
}

// row stride in bytes for bf16 tiles (136 halves): ldmatrix conflict-free
#define SR 272
// ldmatrix address helpers (tiles are row-major [rows][136 halves])
__device__ __forceinline__ u32 a_addr(u32 base, int m0, int k0, int lane) {
    int r  = m0 + (lane & 7) + ((lane >> 3) & 1) * 8;
    int kc = k0 + (lane >> 4) * 8;
    return base + r * SR + kc * 2;
}
__device__ __forceinline__ u32 b_addr(u32 base, int n0, int k0, int lane) {
    int r  = n0 + (lane & 7);
    int kc = k0 + ((lane >> 3) & 1) * 8;
    return base + r * SR + kc * 2;
}

// Scratch
__device__ float d_phiq[(size_t)NTOK*Mm];
__device__ float d_phik[(size_t)NTOK*Mm];
__device__ float d_S[(size_t)BH*NC*Mm*Dd];
__device__ float d_zz[BH*NC*Mm];
__device__ float d_bmax[NBT];
__device__ float d_gmax;

// ---------------------------------------------------------------------------
// K1: proj = (x*scale) @ omega^T for q and k (unchanged)
// ---------------------------------------------------------------------------
__global__ __launch_bounds__(256) void k_proj(const float* __restrict__ qg,
                                              const float* __restrict__ kg,
                                              const float* __restrict__ omg) {
    extern __shared__ float sm[];
    float* xsT = sm;               // [64][132]
    float* omT = sm + 64*132;      // [64][132]
    float* ss  = sm + 2*64*132;    // [128]
    float* red = ss + 128;         // [2048]

    const int bid = blockIdx.x;
    const bool isq = bid < NBT;
    const int tb  = isq ? bid : bid - NBT;
    const float* xg = (isq ? qg : kg) + (size_t)tb * CH * Dd;
    const int tid = threadIdx.x;

    #pragma unroll
    for (int rep = 0; rep < 8; rep++) {
        int idx = rep*256 + tid;
        int i  = idx >> 4;
        int d4 = (idx & 15) << 2;
        float4 t = *reinterpret_cast<const float4*>(xg + i*Dd + d4);
        xsT[(d4+0)*132 + i] = t.x * SCALE;
        xsT[(d4+1)*132 + i] = t.y * SCALE;
        xsT[(d4+2)*132 + i] = t.z * SCALE;
        xsT[(d4+3)*132 + i] = t.w * SCALE;
    }
    #pragma unroll
    for (int rep = 0; rep < 8; rep++) {
        int idx = rep*256 + tid;
        int m  = idx >> 4;
        int d4 = (idx & 15) << 2;
        float4 t = *reinterpret_cast<const float4*>(omg + m*Dd + d4);
        omT[(d4+0)*132 + m] = t.x;
        omT[(d4+1)*132 + m] = t.y;
        omT[(d4+2)*132 + m] = t.z;
        omT[(d4+3)*132 + m] = t.w;
    }
    __syncthreads();
    if (tid < 128) {
        float s = 0.f;
        #pragma unroll
        for (int d = 0; d < 64; d++) { float vv = xsT[d*132 + tid]; s = fmaf(vv, vv, s); }
        ss[tid] = 0.5f * s;
    }
    __syncthreads();

    const int tx = tid & 15, ty = tid >> 4;
    const int i0 = ty*8, m0 = tx*8;
    u64 acc2[8][4];
    #pragma unroll
    for (int u = 0; u < 8; u++)
        #pragma unroll
        for (int w = 0; w < 4; w++) acc2[u][w] = 0ull;

    for (int d = 0; d < 64; d++) {
        float a[8];
        float4 t;
        t = *reinterpret_cast<const float4*>(&xsT[d*132 + i0]);     a[0]=t.x;a[1]=t.y;a[2]=t.z;a[3]=t.w;
        t = *reinterpret_cast<const float4*>(&xsT[d*132 + i0 + 4]); a[4]=t.x;a[5]=t.y;a[6]=t.z;a[7]=t.w;
        u64 a2[8];
        #pragma unroll
        for (int u = 0; u < 8; u++) a2[u] = pk2(a[u], a[u]);
        ulonglong2 bb0 = *reinterpret_cast<const ulonglong2*>(&omT[d*132 + m0]);
        ulonglong2 bb1 = *reinterpret_cast<const ulonglong2*>(&omT[d*132 + m0 + 4]);
        u64 b2[4] = {bb0.x, bb0.y, bb1.x, bb1.y};
        #pragma unroll
        for (int u = 0; u < 8; u++)
            #pragma unroll
            for (int w = 0; w < 4; w++) acc2[u][w] = ffma2(a2[u], b2[w], acc2[u][w]);
    }
    float acc[8][8];
    #pragma unroll
    for (int u = 0; u < 8; u++)
        #pragma unroll
        for (int w = 0; w < 4; w++) upk2(acc2[u][w], acc[u][2*w], acc[u][2*w+1]);

    const size_t tok0 = (size_t)tb * CH;
    if (isq) {
        #pragma unroll
        for (int u = 0; u < 8; u++) {
            float m = acc[u][0];
            #pragma unroll
            for (int w = 1; w < 8; w++) m = fmaxf(m, acc[u][w]);
            red[(i0+u)*16 + tx] = m;
        }
        __syncthreads();
        if (tid < 128) {
            float m = red[tid*16];
            #pragma unroll
            for (int t = 1; t < 16; t++) m = fmaxf(m, red[tid*16 + t]);
            ss[tid] = m;
        }
        __syncthreads();
        float* og = d_phiq + tok0 * Mm;
        #pragma unroll
        for (int u = 0; u < 8; u++) {
            float rm = ss[i0+u];
            float4 s0, s1;
            s0.x = __expf(acc[u][0]-rm)*INV_SQRT_M + EPS_PHI;
            s0.y = __expf(acc[u][1]-rm)*INV_SQRT_M + EPS_PHI;
            s0.z = __expf(acc[u][2]-rm)*INV_SQRT_M + EPS_PHI;
            s0.w = __expf(acc[u][3]-rm)*INV_SQRT_M + EPS_PHI;
            s1.x = __expf(acc[u][4]-rm)*INV_SQRT_M + EPS_PHI;
            s1.y = __expf(acc[u][5]-rm)*INV_SQRT_M + EPS_PHI;
            s1.z = __expf(acc[u][6]-rm)*INV_SQRT_M + EPS_PHI;
            s1.w = __expf(acc[u][7]-rm)*INV_SQRT_M + EPS_PHI;
            *reinterpret_cast<float4*>(og + (size_t)(i0+u)*Mm + m0)     = s0;
            *reinterpret_cast<float4*>(og + (size_t)(i0+u)*Mm + m0 + 4) = s1;
        }
    } else {
        float bm = -3.0e38f;
        float* og = d_phik + tok0 * Mm;
        #pragma unroll
        for (int u = 0; u < 8; u++) {
            float sr = ss[i0+u];
            #pragma unroll
            for (int w = 0; w < 8; w++) { acc[u][w] -= sr; bm = fmaxf(bm, acc[u][w]); }
            float4 s0, s1;
            s0.x=acc[u][0]; s0.y=acc[u][1]; s0.z=acc[u][2]; s0.w=acc[u][3];
            s1.x=acc[u][4]; s1.y=acc[u][5]; s1.z=acc[u][6]; s1.w=acc[u][7];
            *reinterpret_cast<float4*>(og + (size_t)(i0+u)*Mm + m0)     = s0;
            *reinterpret_cast<float4*>(og + (size_t)(i0+u)*Mm + m0 + 4) = s1;
        }
        red[tid] = bm;
        __syncthreads();
        for (int s = 128; s > 0; s >>= 1) {
            if (tid < s) red[tid] = fmaxf(red[tid], red[tid+s]);
            __syncthreads();
        }
        if (tid == 0) d_bmax[tb] = red[0];
    }
}

__global__ __launch_bounds__(256) void k_gmax() {
    __shared__ float red[256];
    const int tid = threadIdx.x;
    float m = -3.0e38f;
    for (int i = tid; i < NBT; i += 256) m = fmaxf(m, d_bmax[i]);
    red[tid] = m;
    __syncthreads();
    for (int s = 128; s > 0; s >>= 1) {
        if (tid < s) red[tid] = fmaxf(red[tid], red[tid+s]);
        __syncthreads();
    }
    if (tid == 0) d_gmax = red[0];
}

// ---------------------------------------------------------------------------
// K2: phi_k = exp(lp-gmax)/sqrt(M)+eps; chunk sums (unchanged)
// ---------------------------------------------------------------------------
__global__ __launch_bounds__(256) void k_phik_sums(const float* __restrict__ vg) {
    extern __shared__ float sm[];
    float* phis = sm;            // [128][128]
    float* vs   = sm + 128*128;  // [128][64]
    const int bid = blockIdx.x;
    const int bh = bid >> 5, c = bid & 31;
    const size_t tok0 = (size_t)bh * Nn + (size_t)c * CH;
    const int tid = threadIdx.x;
    const float gm = d_gmax;

    float* pk = d_phik + tok0 * Mm;
    #pragma unroll
    for (int rep = 0; rep < 16; rep++) {
        int idx = (rep*256 + tid) * 4;
        float4 t = *reinterpret_cast<const float4*>(pk + idx);
        t.x = __expf(t.x-gm)*INV_SQRT_M + EPS_PHI;
        t.y = __expf(t.y-gm)*INV_SQRT_M + EPS_PHI;
        t.z = __expf(t.z-gm)*INV_SQRT_M + EPS_PHI;
        t.w = __expf(t.w-gm)*INV_SQRT_M + EPS_PHI;
        *reinterpret_cast<float4*>(pk + idx)   = t;
        *reinterpret_cast<float4*>(phis + idx) = t;
    }
    #pragma unroll
    for (int rep = 0; rep < 8; rep++) {
        int idx = (rep*256 + tid) * 4;
        *reinterpret_cast<float4*>(vs + idx) =
            *reinterpret_cast<const float4*>(vg + tok0*Dd + idx);
    }
    __syncthreads();

    const int tx = tid & 15, ty = tid >> 4;
    const int m0 = ty*8, d0 = tx*4;
    u64 acc2[8][2];
    float zacc[8];
    #pragma unroll
    for (int u = 0; u < 8; u++) {
        zacc[u] = 0.f;
        acc2[u][0] = 0ull; acc2[u][1] = 0ull;
    }
    for (int i = 0; i < 128; i++) {
        float a[8];
        float4 t;
        t = *reinterpret_cast<const float4*>(&phis[i*128 + m0]);     a[0]=t.x;a[1]=t.y;a[2]=t.z;a[3]=t.w;
        t = *reinterpret_cast<const float4*>(&phis[i*128 + m0 + 4]); a[4]=t.x;a[5]=t.y;a[6]=t.z;a[7]=t.w;
        u64 a2[8];
        #pragma unroll
        for (int u = 0; u < 8; u++) a2[u] = pk2(a[u], a[u]);
        ulonglong2 bb = *reinterpret_cast<const ulonglong2*>(&vs[i*64 + d0]);
        #pragma unroll
        for (int u = 0; u < 8; u++) {
            acc2[u][0] = ffma2(a2[u], bb.x, acc2[u][0]);
            acc2[u][1] = ffma2(a2[u], bb.y, acc2[u][1]);
        }
        if (tx == 0) {
            #pragma unroll
            for (int u = 0; u < 8; u++) zacc[u] += a[u];
        }
    }
    float* Sg = d_S + (size_t)(bh*NC + c) * (Mm*Dd);
    #pragma unroll
    for (int u = 0; u < 8; u++) {
        float4 t;
        upk2(acc2[u][0], t.x, t.y);
        upk2(acc2[u][1], t.z, t.w);
        *reinterpret_cast<float4*>(Sg + (m0+u)*Dd + d0) = t;
    }
    if (tx == 0) {
        float* zg = d_zz + (bh*NC + c) * Mm;
        #pragma unroll
        for (int u = 0; u < 8; u++) zg[m0+u] = zacc[u];
    }
}

// ---------------------------------------------------------------------------
// K3: exclusive prefix over the 32 chunks (unchanged)
// ---------------------------------------------------------------------------
__global__ __launch_bounds__(256) void k_scan() {
    const int gid = blockIdx.x * 256 + threadIdx.x;
    if (blockIdx.x < 2048) {
        const int bh = gid >> 13;
        const int e  = gid & 8191;
        const size_t p = (size_t)bh * NC * (Mm*Dd) + e;
        float v[NC];
        #pragma unroll
        for (int c = 0; c < NC; c++) v[c] = d_S[p + (size_t)c * (Mm*Dd)];
        float acc = 0.f;
        #pragma unroll
        for (int c = 0; c < NC; c++) {
            d_S[p + (size_t)c * (Mm*Dd)] = acc;
            acc += v[c];
        }
    } else {
        const int idx = gid - 2048*256;
        const int bh = idx >> 7, m = idx & 127;
        const size_t p = (size_t)bh * NC * Mm + m;
        float v[NC];
        #pragma unroll
        for (int c = 0; c < NC; c++) v[c] = d_zz[p + c*Mm];
        float acc = 0.f;
        #pragma unroll
        for (int c = 0; c < NC; c++) {
            d_zz[p + c*Mm] = acc;
            acc += v[c];
        }
    }
}

// ---------------------------------------------------------------------------
// K4 (warp-MMA): per 128-token chunk, 8 warps, each owning a 16-row i-block.
//   GEMM1: A = phiq . phik^T  (bf16 split, causal tiles only)
//   mask in registers -> bf16 split -> overwrite phik tiles
//   GEMM2: D2[128,72] = A.VT + phiq.ST   (VT row64 = 1, ST row64 = z -> den)
//   out = D2[:,0:64] / (D2[:,64] + eps)
// smem tiles row-major bf16, stride 136 halves (272 B)
// ---------------------------------------------------------------------------
#define OF_DEN 0
#define SQ_HI  1024
#define SQ_LO  (SQ_HI + 34816)
#define SK_HI  (SQ_LO + 34816)
#define SK_LO  (SK_HI + 34816)
#define SV_HI  (SK_LO + 34816)
#define SV_LO  (SV_HI + 19584)
#define SS_HI  (SV_LO + 19584)
#define SS_LO  (SS_HI + 19584)
#define SM4T   (SS_LO + 19584)   // 218624 bytes

__global__ __launch_bounds__(256) void k_out_mma(const float* __restrict__ vg,
                                                 float* __restrict__ outg) {
    extern __shared__ char smc[];
    const u32 sb = s2u(smc);
    float* den_s = (float*)(smc + OF_DEN);
    const int tid = threadIdx.x, wid = tid >> 5, lane = tid & 31;
    const int bid = blockIdx.x, bh = bid >> 5, c = bid & 31;
    const size_t tok0 = (size_t)bh * Nn + (size_t)c * CH;

    // ---- stage phi_q, phi_k tiles (bf16 hi/lo, row-major [128][136]) ----
    const float* pqg = d_phiq + tok0 * Mm;
    const float* pkg = d_phik + tok0 * Mm;
    #pragma unroll
    for (int it = 0; it < 16; it++) {
        int idx = (it*256 + tid) * 4;
        int r = idx >> 7, cc = idx & 127;
        u32 off = (u32)r * SR + (u32)cc * 2;
        float4 t = *reinterpret_cast<const float4*>(pqg + idx);
        unsigned short h0,l0,h1,l1,h2,l2,h3,l3;
        split2(t.x,h0,l0); split2(t.y,h1,l1); split2(t.z,h2,l2); split2(t.w,h3,l3);
        *(u32*)(smc+SQ_HI+off)   = (u32)h0 | ((u32)h1<<16);
        *(u32*)(smc+SQ_HI+off+4) = (u32)h2 | ((u32)h3<<16);
        *(u32*)(smc+SQ_LO+off)   = (u32)l0 | ((u32)l1<<16);
        *(u32*)(smc+SQ_LO+off+4) = (u32)l2 | ((u32)l3<<16);
        t = *reinterpret_cast<const float4*>(pkg + idx);
        split2(t.x,h0,l0); split2(t.y,h1,l1); split2(t.z,h2,l2); split2(t.w,h3,l3);
        *(u32*)(smc+SK_HI+off)   = (u32)h0 | ((u32)h1<<16);
        *(u32*)(smc+SK_HI+off+4) = (u32)h2 | ((u32)h3<<16);
        *(u32*)(smc+SK_LO+off)   = (u32)l0 | ((u32)l1<<16);
        *(u32*)(smc+SK_LO+off+4) = (u32)l2 | ((u32)l3<<16);
    }

    // ---- stage VT [72][128] (V^T) and ST [72][128] (S^T), split ----
    const float* Sg = d_S + (size_t)(bh*NC + c) * (Mm*Dd);
    #pragma unroll
    for (int it = 0; it < 4; it++) {
        int t4 = it*256 + tid;                 // 0..1023
        int jp = t4 >> 4, dg = (t4 & 15) << 2; // col pair j=2jp, rows dg..dg+3
        float4 va = *reinterpret_cast<const float4*>(vg + (tok0 + 2*jp)*Dd + dg);
        float4 vb = *reinterpret_cast<const float4*>(vg + (tok0 + 2*jp + 1)*Dd + dg);
        float fa[4] = {va.x, va.y, va.z, va.w};
        float fb[4] = {vb.x, vb.y, vb.z, vb.w};
        #pragma unroll
        for (int e = 0; e < 4; e++) {
            unsigned short ha,la,hb,lb;
            split2(fa[e], ha, la); split2(fb[e], hb, lb);
            u32 off = (u32)(dg+e) * SR + (u32)jp * 4;
            *(u32*)(smc+SV_HI+off) = (u32)ha | ((u32)hb<<16);
            *(u32*)(smc+SV_LO+off) = (u32)la | ((u32)lb<<16);
        }
        va = *reinterpret_cast<const float4*>(Sg + (2*jp)*Dd + dg);
        vb = *reinterpret_cast<const float4*>(Sg + (2*jp + 1)*Dd + dg);
        float ga[4] = {va.x, va.y, va.z, va.w};
        float gb[4] = {vb.x, vb.y, vb.z, vb.w};
        #pragma unroll
        for (int e = 0; e < 4; e++) {
            unsigned short ha,la,hb,lb;
            split2(ga[e], ha, la); split2(gb[e], hb, lb);
            u32 off = (u32)(dg+e) * SR + (u32)jp * 4;
            *(u32*)(smc+SS_HI+off) = (u32)ha | ((u32)hb<<16);
            *(u32*)(smc+SS_LO+off) = (u32)la | ((u32)lb<<16);
        }
    }
    // row 64: ones (VT) / z (ST); rows 65..71 zero
    if (tid < 64) {
        int cp = tid * 2;
        u32 off = 64u * SR + (u32)tid * 4;
        *(u32*)(smc+SV_HI+off) = 0x3F803F80u;
        *(u32*)(smc+SV_LO+off) = 0u;
        const float* zg = d_zz + (bh*NC + c) * Mm;
        unsigned short h0,l0,h1,l1;
        split2(zg[cp],   h0, l0);
        split2(zg[cp+1], h1, l1);
        *(u32*)(smc+SS_HI+off) = (u32)h0 | ((u32)h1<<16);
        *(u32*)(smc+SS_LO+off) = (u32)l0 | ((u32)l1<<16);
    }
    for (int t4 = tid; t4 < 7*64; t4 += 256) {
        int r = 65 + t4/64;
        u32 off = (u32)r * SR + (u32)(t4 % 64) * 4;
        *(u32*)(smc+SV_HI+off) = 0u;
        *(u32*)(smc+SV_LO+off) = 0u;
        *(u32*)(smc+SS_HI+off) = 0u;
        *(u32*)(smc+SS_LO+off) = 0u;
    }
    __syncthreads();

    // warp -> i-block (permuted for SMSP load balance under causal skipping)
    const int ib = (wid < 4) ? wid : (7 - (wid - 4));
    const int i0 = ib * 16;
    const int ntmax1 = 2*ib + 1;   // last j-tile with any unmasked element

    // ---- GEMM1: A = phiq . phik^T (rows i0..i0+15, tiles 0..ntmax1) ----
    float acc[16][4];
    #pragma unroll
    for (int nt = 0; nt < 16; nt++)
        #pragma unroll
        for (int e = 0; e < 4; e++) acc[nt][e] = 0.f;

    for (int kk = 0; kk < 8; kk++) {
        int k0 = kk * 16;
        u32 qh0,qh1,qh2,qh3, ql0,ql1,ql2,ql3;
        ldsm4(qh0,qh1,qh2,qh3, a_addr(sb+SQ_HI, i0, k0, lane));
        ldsm4(ql0,ql1,ql2,ql3, a_addr(sb+SQ_LO, i0, k0, lane));
        #pragma unroll
        for (int nt = 0; nt < 16; nt++) {
            if (nt > ntmax1) break;
            u32 bh0,bh1, bl0,bl1;
            ldsm2(bh0,bh1, b_addr(sb+SK_HI, nt*8, k0, lane));
            ldsm2(bl0,bl1, b_addr(sb+SK_LO, nt*8, k0, lane));
            mma16816(acc[nt], qh0,qh1,qh2,qh3, bh0,bh1);
            mma16816(acc[nt], qh0,qh1,qh2,qh3, bl0,bl1);
            mma16816(acc[nt], ql0,ql1,ql2,ql3, bh0,bh1);
        }
    }

    __syncthreads();   // all warps done reading phik tiles

    // ---- mask causal in registers, split, overwrite phik tiles ----
    {
        const int m1 = i0 + (lane >> 2);
        const int m2 = m1 + 8;
        #pragma unroll
        for (int nt = 0; nt < 16; nt++) {
            if (nt > ntmax1) break;
            int jj = nt*8 + 2*(lane & 3);
            float a0 = (jj     <= m1) ? acc[nt][0] : 0.f;
            float a1 = (jj + 1 <= m1) ? acc[nt][1] : 0.f;
            float a2 = (jj     <= m2) ? acc[nt][2] : 0.f;
            float a3 = (jj + 1 <= m2) ? acc[nt][3] : 0.f;
            unsigned short h0,l0,h1,l1;
            split2(a0, h0, l0); split2(a1, h1, l1);
            u32 off = (u32)m1 * SR + (u32)jj * 2;
            *(u32*)(smc+SK_HI+off) = (u32)h0 | ((u32)h1<<16);
            *(u32*)(smc+SK_LO+off) = (u32)l0 | ((u32)l1<<16);
            split2(a2, h0, l0); split2(a3, h1, l1);
            off = (u32)m2 * SR + (u32)jj * 2;
            *(u32*)(smc+SK_HI+off) = (u32)h0 | ((u32)h1<<16);
            *(u32*)(smc+SK_LO+off) = (u32)l0 | ((u32)l1<<16);
        }
    }
    __syncwarp();   // only this warp re-reads its own rows

    // ---- GEMM2: D2 = A.VT + phiq.ST  (N = 72, col 64 = denominator) ----
    float o[9][4];
    #pragma unroll
    for (int nt = 0; nt < 9; nt++)
        #pragma unroll
        for (int e = 0; e < 4; e++) o[nt][e] = 0.f;

    for (int kk = 0; kk < 8; kk++) {
        int k0 = kk * 16;
        u32 qh0,qh1,qh2,qh3, ql0,ql1,ql2,ql3;
        ldsm4(qh0,qh1,qh2,qh3, a_addr(sb+SQ_HI, i0, k0, lane));
        ldsm4(ql0,ql1,ql2,ql3, a_addr(sb+SQ_LO, i0, k0, lane));
        const bool doA = (kk <= ib);   // A cols beyond i0+15 are zero
        u32 ah0=0,ah1=0,ah2=0,ah3=0, al0=0,al1=0,al2=0,al3=0;
        if (doA) {
            ldsm4(ah0,ah1,ah2,ah3, a_addr(sb+SK_HI, i0, k0, lane));
            ldsm4(al0,al1,al2,al3, a_addr(sb+SK_LO, i0, k0, lane));
        }
        #pragma unroll
        for (int nt = 0; nt < 9; nt++) {
            u32 sh0,sh1, sl0,sl1;
            ldsm2(sh0,sh1, b_addr(sb+SS_HI, nt*8, k0, lane));
            ldsm2(sl0,sl1, b_addr(sb+SS_LO, nt*8, k0, lane));
            mma16816(o[nt], qh0,qh1,qh2,qh3, sh0,sh1);
            mma16816(o[nt], qh0,qh1,qh2,qh3, sl0,sl1);
            mma16816(o[nt], ql0,ql1,ql2,ql3, sh0,sh1);
            if (doA) {
                u32 vh0,vh1, vl0,vl1;
                ldsm2(vh0,vh1, b_addr(sb+SV_HI, nt*8, k0, lane));
                ldsm2(vl0,vl1, b_addr(sb+SV_LO, nt*8, k0, lane));
                mma16816(o[nt], ah0,ah1,ah2,ah3, vh0,vh1);
                mma16816(o[nt], ah0,ah1,ah2,ah3, vl0,vl1);
                mma16816(o[nt], al0,al1,al2,al3, vh0,vh1);
            }
        }
    }

    // ---- epilogue: den from col 64, write out ----
    if ((lane & 3) == 0) {
        den_s[i0 + (lane >> 2)]     = 1.f / (o[8][0] + EPS_DEN);
        den_s[i0 + 8 + (lane >> 2)] = 1.f / (o[8][2] + EPS_DEN);
    }
    __syncwarp();
    {
        const int m1 = i0 + (lane >> 2);
        const int m2 = m1 + 8;
        const float inv1 = den_s[m1];
        const float inv2 = den_s[m2];
        #pragma unroll
        for (int nt = 0; nt < 8; nt++) {
            int n = nt*8 + 2*(lane & 3);
            float2 t1 = { o[nt][0]*inv1, o[nt][1]*inv1 };
            float2 t2 = { o[nt][2]*inv2, o[nt][3]*inv2 };
            *reinterpret_cast<float2*>(outg + (tok0 + m1)*Dd + n) = t1;
            *reinterpret_cast<float2*>(outg + (tok0 + m2)*Dd + n) = t2;
        }
    }
}

// ---------------------------------------------------------------------------

extern "C" void kernel_launch(void* const* d_in, const int* in_sizes, int n_in,
                              void* d_out, int out_size) {
    const float* q  = (const float*)d_in[0];
    const float* k  = (const float*)d_in[1];
    const float* v  = (const float*)d_in[2];
    const float* om = (const float*)d_in[3];
    float* out = (float*)d_out;

    const int SM1 = 19072 * 4;   // 76288
    const int SM2 = 24576 * 4;   // 98304
    cudaFuncSetAttribute(k_proj,      cudaFuncAttributeMaxDynamicSharedMemorySize, SM1);
    cudaFuncSetAttribute(k_phik_sums, cudaFuncAttributeMaxDynamicSharedMemorySize, SM2);
    cudaFuncSetAttribute(k_out_mma,   cudaFuncAttributeMaxDynamicSharedMemorySize, SM4T);

    k_proj<<<2*NBT, 256, SM1>>>(q, k, om);
    k_gmax<<<1, 256>>>();
    k_phik_sums<<<NBT, 256, SM2>>>(v);
    k_scan<<<2048 + 32, 256>>>();
    k_out_mma<<<NBT, 256, SM4T>>>(v, out);
}

// round 6
// speedup vs baseline: 2.4444x; 1.2596x over previous
#include <cuda_runtime.h>
#include <cuda_bf16.h>
#include <cstdint>

#define SCALE       0.35355339059327373f   // 64^(-1/4)
#define INV_SQRT_M  0.08838834764831843f   // 1/sqrt(128)
#define EPS_PHI     1e-4f
#define EPS_DEN     1e-6f

#define BH    64        // B*H = 4*16
#define Nn    4096
#define Dd    64
#define Mm    128
#define CH    128       // chunk length
#define NC    32        // chunks per head
#define NTOK  (BH*Nn)   // 262144
#define NBT   (NTOK/CH) // 2048 token-chunks

typedef unsigned long long u64;
typedef unsigned int u32;

// ---------------- packed fp32x2 (K2) ----------------
__device__ __forceinline__ u64 pk2(float x, float y) {
    u64 r; asm("mov.b64 %0, {%1,%2};" : "=l"(r) : "f"(x), "f"(y)); return r;
}
__device__ __forceinline__ void upk2(u64 p, float& x, float& y) {
    asm("mov.b64 {%0,%1}, %2;" : "=f"(x), "=f"(y) : "l"(p));
}
__device__ __forceinline__ u64 ffma2(u64 a, u64 b, u64 c) {
    u64 d; asm("fma.rn.f32x2 %0, %1, %2, %3;" : "=l"(d) : "l"(a), "l"(b), "l"(c)); return d;
}

// ---------------- warp MMA helpers ----------------
__device__ __forceinline__ u32 s2u(const void* p) {
    u32 a; asm("{ .reg .u64 t; cvta.to.shared.u64 t, %1; cvt.u32.u64 %0, t; }"
               : "=r"(a) : "l"(p));
    return a;
}
__device__ __forceinline__ void ldsm4(u32& r0, u32& r1, u32& r2, u32& r3, u32 addr) {
    asm volatile("ldmatrix.sync.aligned.m8n8.x4.shared.b16 {%0,%1,%2,%3}, [%4];"
                 : "=r"(r0), "=r"(r1), "=r"(r2), "=r"(r3) : "r"(addr));
}
__device__ __forceinline__ void ldsm2(u32& r0, u32& r1, u32 addr) {
    asm volatile("ldmatrix.sync.aligned.m8n8.x2.shared.b16 {%0,%1}, [%2];"
                 : "=r"(r0), "=r"(r1) : "r"(addr));
}
__device__ __forceinline__ void mma16816(float* d, u32 a0, u32 a1, u32 a2, u32 a3,
                                         u32 b0, u32 b1) {
    asm volatile("mma.sync.aligned.m16n8k16.row.col.f32.bf16.bf16.f32 "
                 "{%0,%1,%2,%3}, {%4,%5,%6,%7}, {%8,%9}, {%0,%1,%2,%3};"
                 : "+f"(d[0]), "+f"(d[1]), "+f"(d[2]), "+f"(d[3])
                 : "r"(a0), "r"(a1), "r"(a2), "r"(a3), "r"(b0), "r"(b1));
}

// bf16 split
__device__ __forceinline__ unsigned short bf16h(float x) {
    unsigned short u; asm("cvt.rn.bf16.f32 %0, %1;" : "=h"(u) : "f"(x)); return u;
}
__device__ __forceinline__ float bf2f(unsigned short u) {
    float f; asm("cvt.f32.bf16 %0, %1;" : "=f"(f) : "h"(u)); return f;
}
__device__ __forceinline__ void split2(float x, unsigned short& h, unsigned short& l) {
    h = bf16h(x); l = bf16h(x - bf2f(h));
}

// K4 tiles: 136-half rows (272 B). K1 tiles: 72-half rows (144 B).
#define SR  272
#define SR1 144
__device__ __forceinline__ u32 a_addr_s(u32 base, int m0, int k0, int lane, int srb) {
    int r  = m0 + (lane & 7) + ((lane >> 3) & 1) * 8;
    int kc = k0 + (lane >> 4) * 8;
    return base + r * srb + kc * 2;
}
__device__ __forceinline__ u32 b_addr_s(u32 base, int n0, int k0, int lane, int srb) {
    int r  = n0 + (lane & 7);
    int kc = k0 + ((lane >> 3) & 1) * 8;
    return base + r * srb + kc * 2;
}
__device__ __forceinline__ u32 a_addr(u32 base, int m0, int k0, int lane) {
    return a_addr_s(base, m0, k0, lane, SR);
}
__device__ __forceinline__ u32 b_addr(u32 base, int n0, int k0, int lane) {
    return b_addr_s(base, n0, k0, lane, SR);
}

// Scratch
__device__ float d_phiq[(size_t)NTOK*Mm];
__device__ float d_phik[(size_t)NTOK*Mm];
__device__ float d_S[(size_t)BH*NC*Mm*Dd];
__device__ float d_zz[BH*NC*Mm];
__device__ float d_bmax[NBT];
__device__ float d_gmax;

// ---------------------------------------------------------------------------
// K1 (warp-MMA): proj[128,128] = (x*scale)[128,64] @ omega^T, bf16 split.
//  q blocks: phi_q = exp(proj - rowmax)/sqrt(M)+eps -> d_phiq
//  k blocks: lp = proj - 0.5||x||^2 -> d_phik, block max -> d_bmax
// smem: ssp[2048] ss[128] red[256] | X_HI X_LO OM_HI OM_LO [128][72h]
// ---------------------------------------------------------------------------
#define P_SSP 0
#define P_SS  8192
#define P_RED 8704
#define P_XH  9728
#define P_XL  (P_XH + 18432)
#define P_OH  (P_XL + 18432)
#define P_OL  (P_OH + 18432)
#define SM1T  (P_OL + 18432)   // 83456 B

__global__ __launch_bounds__(256) void k_proj_mma(const float* __restrict__ qg,
                                                  const float* __restrict__ kg,
                                                  const float* __restrict__ omg) {
    extern __shared__ char smc[];
    const u32 sb = s2u(smc);
    float* ssp = (float*)(smc + P_SSP);
    float* ss  = (float*)(smc + P_SS);
    float* red = (float*)(smc + P_RED);

    const int bid = blockIdx.x;
    const bool isq = bid < NBT;
    const int tb  = isq ? bid : bid - NBT;
    const float* xg = (isq ? qg : kg) + (size_t)tb * CH * Dd;
    const int tid = threadIdx.x, wid = tid >> 5, lane = tid & 31;

    // ---- stage x (scaled, split, + norm partials) and omega (split) ----
    #pragma unroll
    for (int it = 0; it < 8; it++) {
        int f4g = it*256 + tid;          // 0..2047
        int r = f4g >> 4, p = f4g & 15, c4 = p * 4;
        u32 off = (u32)r * SR1 + (u32)c4 * 2;
        float4 t = *reinterpret_cast<const float4*>(xg + r*Dd + c4);
        t.x *= SCALE; t.y *= SCALE; t.z *= SCALE; t.w *= SCALE;
        ssp[f4g] = t.x*t.x + t.y*t.y + t.z*t.z + t.w*t.w;
        unsigned short h0,l0,h1,l1,h2,l2,h3,l3;
        split2(t.x,h0,l0); split2(t.y,h1,l1); split2(t.z,h2,l2); split2(t.w,h3,l3);
        *(u32*)(smc+P_XH+off)   = (u32)h0 | ((u32)h1<<16);
        *(u32*)(smc+P_XH+off+4) = (u32)h2 | ((u32)h3<<16);
        *(u32*)(smc+P_XL+off)   = (u32)l0 | ((u32)l1<<16);
        *(u32*)(smc+P_XL+off+4) = (u32)l2 | ((u32)l3<<16);
        float4 w = *reinterpret_cast<const float4*>(omg + (size_t)f4g * 4);
        split2(w.x,h0,l0); split2(w.y,h1,l1); split2(w.z,h2,l2); split2(w.w,h3,l3);
        *(u32*)(smc+P_OH+off)   = (u32)h0 | ((u32)h1<<16);
        *(u32*)(smc+P_OH+off+4) = (u32)h2 | ((u32)h3<<16);
        *(u32*)(smc+P_OL+off)   = (u32)l0 | ((u32)l1<<16);
        *(u32*)(smc+P_OL+off+4) = (u32)l2 | ((u32)l3<<16);
    }
    __syncthreads();
    if (tid < 128) {
        float s = 0.f;
        #pragma unroll
        for (int j = 0; j < 16; j++) s += ssp[tid*16 + j];
        ss[tid] = 0.5f * s;
    }
    __syncthreads();

    // ---- GEMM: warp wid owns rows i0..i0+15, full N=128, K=64 ----
    const int i0 = wid * 16;
    float acc[16][4];
    #pragma unroll
    for (int nt = 0; nt < 16; nt++)
        #pragma unroll
        for (int e = 0; e < 4; e++) acc[nt][e] = 0.f;

    #pragma unroll
    for (int kk = 0; kk < 4; kk++) {
        int k0 = kk * 16;
        u32 xh0,xh1,xh2,xh3, xl0,xl1,xl2,xl3;
        ldsm4(xh0,xh1,xh2,xh3, a_addr_s(sb+P_XH, i0, k0, lane, SR1));
        ldsm4(xl0,xl1,xl2,xl3, a_addr_s(sb+P_XL, i0, k0, lane, SR1));
        #pragma unroll
        for (int nt = 0; nt < 16; nt++) {
            u32 oh0,oh1, ol0,ol1;
            ldsm2(oh0,oh1, b_addr_s(sb+P_OH, nt*8, k0, lane, SR1));
            ldsm2(ol0,ol1, b_addr_s(sb+P_OL, nt*8, k0, lane, SR1));
            mma16816(acc[nt], xh0,xh1,xh2,xh3, oh0,oh1);
            mma16816(acc[nt], xh0,xh1,xh2,xh3, ol0,ol1);
            mma16816(acc[nt], xl0,xl1,xl2,xl3, oh0,oh1);
        }
    }

    const int m1 = i0 + (lane >> 2);
    const int m2 = m1 + 8;
    const size_t tok0 = (size_t)tb * CH;

    if (isq) {
        // rowmax in registers + quad shuffle
        float rm1 = -3.0e38f, rm2 = -3.0e38f;
        #pragma unroll
        for (int nt = 0; nt < 16; nt++) {
            rm1 = fmaxf(rm1, fmaxf(acc[nt][0], acc[nt][1]));
            rm2 = fmaxf(rm2, fmaxf(acc[nt][2], acc[nt][3]));
        }
        rm1 = fmaxf(rm1, __shfl_xor_sync(0xFFFFFFFFu, rm1, 1));
        rm1 = fmaxf(rm1, __shfl_xor_sync(0xFFFFFFFFu, rm1, 2));
        rm2 = fmaxf(rm2, __shfl_xor_sync(0xFFFFFFFFu, rm2, 1));
        rm2 = fmaxf(rm2, __shfl_xor_sync(0xFFFFFFFFu, rm2, 2));
        float* og = d_phiq + tok0 * Mm;
        #pragma unroll
        for (int nt = 0; nt < 16; nt++) {
            int jj = nt*8 + 2*(lane & 3);
            float2 t1, t2;
            t1.x = __expf(acc[nt][0]-rm1)*INV_SQRT_M + EPS_PHI;
            t1.y = __expf(acc[nt][1]-rm1)*INV_SQRT_M + EPS_PHI;
            t2.x = __expf(acc[nt][2]-rm2)*INV_SQRT_M + EPS_PHI;
            t2.y = __expf(acc[nt][3]-rm2)*INV_SQRT_M + EPS_PHI;
            *reinterpret_cast<float2*>(og + (size_t)m1*Mm + jj) = t1;
            *reinterpret_cast<float2*>(og + (size_t)m2*Mm + jj) = t2;
        }
    } else {
        const float s1 = ss[m1], s2 = ss[m2];
        float bm = -3.0e38f;
        float* og = d_phik + tok0 * Mm;
        #pragma unroll
        for (int nt = 0; nt < 16; nt++) {
            int jj = nt*8 + 2*(lane & 3);
            float2 t1, t2;
            t1.x = acc[nt][0] - s1; t1.y = acc[nt][1] - s1;
            t2.x = acc[nt][2] - s2; t2.y = acc[nt][3] - s2;
            bm = fmaxf(bm, fmaxf(fmaxf(t1.x, t1.y), fmaxf(t2.x, t2.y)));
            *reinterpret_cast<float2*>(og + (size_t)m1*Mm + jj) = t1;
            *reinterpret_cast<float2*>(og + (size_t)m2*Mm + jj) = t2;
        }
        red[tid] = bm;
        __syncthreads();
        for (int s = 128; s > 0; s >>= 1) {
            if (tid < s) red[tid] = fmaxf(red[tid], red[tid+s]);
            __syncthreads();
        }
        if (tid == 0) d_bmax[tb] = red[0];
    }
}

__global__ __launch_bounds__(256) void k_gmax() {
    __shared__ float red[256];
    const int tid = threadIdx.x;
    float m = -3.0e38f;
    for (int i = tid; i < NBT; i += 256) m = fmaxf(m, d_bmax[i]);
    red[tid] = m;
    __syncthreads();
    for (int s = 128; s > 0; s >>= 1) {
        if (tid < s) red[tid] = fmaxf(red[tid], red[tid+s]);
        __syncthreads();
    }
    if (tid == 0) d_gmax = red[0];
}

// ---------------------------------------------------------------------------
// K2: phi_k = exp(lp-gmax)/sqrt(M)+eps; chunk sums (unchanged scalar)
// ---------------------------------------------------------------------------
__global__ __launch_bounds__(256) void k_phik_sums(const float* __restrict__ vg) {
    extern __shared__ float sm[];
    float* phis = sm;            // [128][128]
    float* vs   = sm + 128*128;  // [128][64]
    const int bid = blockIdx.x;
    const int bh = bid >> 5, c = bid & 31;
    const size_t tok0 = (size_t)bh * Nn + (size_t)c * CH;
    const int tid = threadIdx.x;
    const float gm = d_gmax;

    float* pk = d_phik + tok0 * Mm;
    #pragma unroll
    for (int rep = 0; rep < 16; rep++) {
        int idx = (rep*256 + tid) * 4;
        float4 t = *reinterpret_cast<const float4*>(pk + idx);
        t.x = __expf(t.x-gm)*INV_SQRT_M + EPS_PHI;
        t.y = __expf(t.y-gm)*INV_SQRT_M + EPS_PHI;
        t.z = __expf(t.z-gm)*INV_SQRT_M + EPS_PHI;
        t.w = __expf(t.w-gm)*INV_SQRT_M + EPS_PHI;
        *reinterpret_cast<float4*>(pk + idx)   = t;
        *reinterpret_cast<float4*>(phis + idx) = t;
    }
    #pragma unroll
    for (int rep = 0; rep < 8; rep++) {
        int idx = (rep*256 + tid) * 4;
        *reinterpret_cast<float4*>(vs + idx) =
            *reinterpret_cast<const float4*>(vg + tok0*Dd + idx);
    }
    __syncthreads();

    const int tx = tid & 15, ty = tid >> 4;
    const int m0 = ty*8, d0 = tx*4;
    u64 acc2[8][2];
    float zacc[8];
    #pragma unroll
    for (int u = 0; u < 8; u++) {
        zacc[u] = 0.f;
        acc2[u][0] = 0ull; acc2[u][1] = 0ull;
    }
    for (int i = 0; i < 128; i++) {
        float a[8];
        float4 t;
        t = *reinterpret_cast<const float4*>(&phis[i*128 + m0]);     a[0]=t.x;a[1]=t.y;a[2]=t.z;a[3]=t.w;
        t = *reinterpret_cast<const float4*>(&phis[i*128 + m0 + 4]); a[4]=t.x;a[5]=t.y;a[6]=t.z;a[7]=t.w;
        u64 a2[8];
        #pragma unroll
        for (int u = 0; u < 8; u++) a2[u] = pk2(a[u], a[u]);
        ulonglong2 bb = *reinterpret_cast<const ulonglong2*>(&vs[i*64 + d0]);
        #pragma unroll
        for (int u = 0; u < 8; u++) {
            acc2[u][0] = ffma2(a2[u], bb.x, acc2[u][0]);
            acc2[u][1] = ffma2(a2[u], bb.y, acc2[u][1]);
        }
        if (tx == 0) {
            #pragma unroll
            for (int u = 0; u < 8; u++) zacc[u] += a[u];
        }
    }
    float* Sg = d_S + (size_t)(bh*NC + c) * (Mm*Dd);
    #pragma unroll
    for (int u = 0; u < 8; u++) {
        float4 t;
        upk2(acc2[u][0], t.x, t.y);
        upk2(acc2[u][1], t.z, t.w);
        *reinterpret_cast<float4*>(Sg + (m0+u)*Dd + d0) = t;
    }
    if (tx == 0) {
        float* zg = d_zz + (bh*NC + c) * Mm;
        #pragma unroll
        for (int u = 0; u < 8; u++) zg[m0+u] = zacc[u];
    }
}

// ---------------------------------------------------------------------------
// K3: exclusive prefix over the 32 chunks (unchanged)
// ---------------------------------------------------------------------------
__global__ __launch_bounds__(256) void k_scan() {
    const int gid = blockIdx.x * 256 + threadIdx.x;
    if (blockIdx.x < 2048) {
        const int bh = gid >> 13;
        const int e  = gid & 8191;
        const size_t p = (size_t)bh * NC * (Mm*Dd) + e;
        float v[NC];
        #pragma unroll
        for (int c = 0; c < NC; c++) v[c] = d_S[p + (size_t)c * (Mm*Dd)];
        float acc = 0.f;
        #pragma unroll
        for (int c = 0; c < NC; c++) {
            d_S[p + (size_t)c * (Mm*Dd)] = acc;
            acc += v[c];
        }
    } else {
        const int idx = gid - 2048*256;
        const int bh = idx >> 7, m = idx & 127;
        const size_t p = (size_t)bh * NC * Mm + m;
        float v[NC];
        #pragma unroll
        for (int c = 0; c < NC; c++) v[c] = d_zz[p + c*Mm];
        float acc = 0.f;
        #pragma unroll
        for (int c = 0; c < NC; c++) {
            d_zz[p + c*Mm] = acc;
            acc += v[c];
        }
    }
}

// ---------------------------------------------------------------------------
// K4 (warp-MMA): unchanged from R5
// ---------------------------------------------------------------------------
#define OF_DEN 0
#define SQ_HI  1024
#define SQ_LO  (SQ_HI + 34816)
#define SK_HI  (SQ_LO + 34816)
#define SK_LO  (SK_HI + 34816)
#define SV_HI  (SK_LO + 34816)
#define SV_LO  (SV_HI + 19584)
#define SS_HI  (SV_LO + 19584)
#define SS_LO  (SS_HI + 19584)
#define SM4T   (SS_LO + 19584)   // 218624 bytes

__global__ __launch_bounds__(256) void k_out_mma(const float* __restrict__ vg,
                                                 float* __restrict__ outg) {
    extern __shared__ char smc[];
    const u32 sb = s2u(smc);
    float* den_s = (float*)(smc + OF_DEN);
    const int tid = threadIdx.x, wid = tid >> 5, lane = tid & 31;
    const int bid = blockIdx.x, bh = bid >> 5, c = bid & 31;
    const size_t tok0 = (size_t)bh * Nn + (size_t)c * CH;

    const float* pqg = d_phiq + tok0 * Mm;
    const float* pkg = d_phik + tok0 * Mm;
    #pragma unroll
    for (int it = 0; it < 16; it++) {
        int idx = (it*256 + tid) * 4;
        int r = idx >> 7, cc = idx & 127;
        u32 off = (u32)r * SR + (u32)cc * 2;
        float4 t = *reinterpret_cast<const float4*>(pqg + idx);
        unsigned short h0,l0,h1,l1,h2,l2,h3,l3;
        split2(t.x,h0,l0); split2(t.y,h1,l1); split2(t.z,h2,l2); split2(t.w,h3,l3);
        *(u32*)(smc+SQ_HI+off)   = (u32)h0 | ((u32)h1<<16);
        *(u32*)(smc+SQ_HI+off+4) = (u32)h2 | ((u32)h3<<16);
        *(u32*)(smc+SQ_LO+off)   = (u32)l0 | ((u32)l1<<16);
        *(u32*)(smc+SQ_LO+off+4) = (u32)l2 | ((u32)l3<<16);
        t = *reinterpret_cast<const float4*>(pkg + idx);
        split2(t.x,h0,l0); split2(t.y,h1,l1); split2(t.z,h2,l2); split2(t.w,h3,l3);
        *(u32*)(smc+SK_HI+off)   = (u32)h0 | ((u32)h1<<16);
        *(u32*)(smc+SK_HI+off+4) = (u32)h2 | ((u32)h3<<16);
        *(u32*)(smc+SK_LO+off)   = (u32)l0 | ((u32)l1<<16);
        *(u32*)(smc+SK_LO+off+4) = (u32)l2 | ((u32)l3<<16);
    }

    const float* Sg = d_S + (size_t)(bh*NC + c) * (Mm*Dd);
    #pragma unroll
    for (int it = 0; it < 4; it++) {
        int t4 = it*256 + tid;
        int jp = t4 >> 4, dg = (t4 & 15) << 2;
        float4 va = *reinterpret_cast<const float4*>(vg + (tok0 + 2*jp)*Dd + dg);
        float4 vb = *reinterpret_cast<const float4*>(vg + (tok0 + 2*jp + 1)*Dd + dg);
        float fa[4] = {va.x, va.y, va.z, va.w};
        float fb[4] = {vb.x, vb.y, vb.z, vb.w};
        #pragma unroll
        for (int e = 0; e < 4; e++) {
            unsigned short ha,la,hb,lb;
            split2(fa[e], ha, la); split2(fb[e], hb, lb);
            u32 off = (u32)(dg+e) * SR + (u32)jp * 4;
            *(u32*)(smc+SV_HI+off) = (u32)ha | ((u32)hb<<16);
            *(u32*)(smc+SV_LO+off) = (u32)la | ((u32)lb<<16);
        }
        va = *reinterpret_cast<const float4*>(Sg + (2*jp)*Dd + dg);
        vb = *reinterpret_cast<const float4*>(Sg + (2*jp + 1)*Dd + dg);
        float ga[4] = {va.x, va.y, va.z, va.w};
        float gb[4] = {vb.x, vb.y, vb.z, vb.w};
        #pragma unroll
        for (int e = 0; e < 4; e++) {
            unsigned short ha,la,hb,lb;
            split2(ga[e], ha, la); split2(gb[e], hb, lb);
            u32 off = (u32)(dg+e) * SR + (u32)jp * 4;
            *(u32*)(smc+SS_HI+off) = (u32)ha | ((u32)hb<<16);
            *(u32*)(smc+SS_LO+off) = (u32)la | ((u32)lb<<16);
        }
    }
    if (tid < 64) {
        int cp = tid * 2;
        u32 off = 64u * SR + (u32)tid * 4;
        *(u32*)(smc+SV_HI+off) = 0x3F803F80u;
        *(u32*)(smc+SV_LO+off) = 0u;
        const float* zg = d_zz + (bh*NC + c) * Mm;
        unsigned short h0,l0,h1,l1;
        split2(zg[cp],   h0, l0);
        split2(zg[cp+1], h1, l1);
        *(u32*)(smc+SS_HI+off) = (u32)h0 | ((u32)h1<<16);
        *(u32*)(smc+SS_LO+off) = (u32)l0 | ((u32)l1<<16);
    }
    for (int t4 = tid; t4 < 7*64; t4 += 256) {
        int r = 65 + t4/64;
        u32 off = (u32)r * SR + (u32)(t4 % 64) * 4;
        *(u32*)(smc+SV_HI+off) = 0u;
        *(u32*)(smc+SV_LO+off) = 0u;
        *(u32*)(smc+SS_HI+off) = 0u;
        *(u32*)(smc+SS_LO+off) = 0u;
    }
    __syncthreads();

    const int ib = (wid < 4) ? wid : (7 - (wid - 4));
    const int i0 = ib * 16;
    const int ntmax1 = 2*ib + 1;

    float acc[16][4];
    #pragma unroll
    for (int nt = 0; nt < 16; nt++)
        #pragma unroll
        for (int e = 0; e < 4; e++) acc[nt][e] = 0.f;

    for (int kk = 0; kk < 8; kk++) {
        int k0 = kk * 16;
        u32 qh0,qh1,qh2,qh3, ql0,ql1,ql2,ql3;
        ldsm4(qh0,qh1,qh2,qh3, a_addr(sb+SQ_HI, i0, k0, lane));
        ldsm4(ql0,ql1,ql2,ql3, a_addr(sb+SQ_LO, i0, k0, lane));
        #pragma unroll
        for (int nt = 0; nt < 16; nt++) {
            if (nt > ntmax1) break;
            u32 bh0,bh1, bl0,bl1;
            ldsm2(bh0,bh1, b_addr(sb+SK_HI, nt*8, k0, lane));
            ldsm2(bl0,bl1, b_addr(sb+SK_LO, nt*8, k0, lane));
            mma16816(acc[nt], qh0,qh1,qh2,qh3, bh0,bh1);
            mma16816(acc[nt], qh0,qh1,qh2,qh3, bl0,bl1);
            mma16816(acc[nt], ql0,ql1,ql2,ql3, bh0,bh1);
        }
    }

    __syncthreads();

    {
        const int m1 = i0 + (lane >> 2);
        const int m2 = m1 + 8;
        #pragma unroll
        for (int nt = 0; nt < 16; nt++) {
            if (nt > ntmax1) break;
            int jj = nt*8 + 2*(lane & 3);
            float a0 = (jj     <= m1) ? acc[nt][0] : 0.f;
            float a1 = (jj + 1 <= m1) ? acc[nt][1] : 0.f;
            float a2 = (jj     <= m2) ? acc[nt][2] : 0.f;
            float a3 = (jj + 1 <= m2) ? acc[nt][3] : 0.f;
            unsigned short h0,l0,h1,l1;
            split2(a0, h0, l0); split2(a1, h1, l1);
            u32 off = (u32)m1 * SR + (u32)jj * 2;
            *(u32*)(smc+SK_HI+off) = (u32)h0 | ((u32)h1<<16);
            *(u32*)(smc+SK_LO+off) = (u32)l0 | ((u32)l1<<16);
            split2(a2, h0, l0); split2(a3, h1, l1);
            off = (u32)m2 * SR + (u32)jj * 2;
            *(u32*)(smc+SK_HI+off) = (u32)h0 | ((u32)h1<<16);
            *(u32*)(smc+SK_LO+off) = (u32)l0 | ((u32)l1<<16);
        }
    }
    __syncwarp();

    float o[9][4];
    #pragma unroll
    for (int nt = 0; nt < 9; nt++)
        #pragma unroll
        for (int e = 0; e < 4; e++) o[nt][e] = 0.f;

    for (int kk = 0; kk < 8; kk++) {
        int k0 = kk * 16;
        u32 qh0,qh1,qh2,qh3, ql0,ql1,ql2,ql3;
        ldsm4(qh0,qh1,qh2,qh3, a_addr(sb+SQ_HI, i0, k0, lane));
        ldsm4(ql0,ql1,ql2,ql3, a_addr(sb+SQ_LO, i0, k0, lane));
        const bool doA = (kk <= ib);
        u32 ah0=0,ah1=0,ah2=0,ah3=0, al0=0,al1=0,al2=0,al3=0;
        if (doA) {
            ldsm4(ah0,ah1,ah2,ah3, a_addr(sb+SK_HI, i0, k0, lane));
            ldsm4(al0,al1,al2,al3, a_addr(sb+SK_LO, i0, k0, lane));
        }
        #pragma unroll
        for (int nt = 0; nt < 9; nt++) {
            u32 sh0,sh1, sl0,sl1;
            ldsm2(sh0,sh1, b_addr(sb+SS_HI, nt*8, k0, lane));
            ldsm2(sl0,sl1, b_addr(sb+SS_LO, nt*8, k0, lane));
            mma16816(o[nt], qh0,qh1,qh2,qh3, sh0,sh1);
            mma16816(o[nt], qh0,qh1,qh2,qh3, sl0,sl1);
            mma16816(o[nt], ql0,ql1,ql2,ql3, sh0,sh1);
            if (doA) {
                u32 vh0,vh1, vl0,vl1;
                ldsm2(vh0,vh1, b_addr(sb+SV_HI, nt*8, k0, lane));
                ldsm2(vl0,vl1, b_addr(sb+SV_LO, nt*8, k0, lane));
                mma16816(o[nt], ah0,ah1,ah2,ah3, vh0,vh1);
                mma16816(o[nt], ah0,ah1,ah2,ah3, vl0,vl1);
                mma16816(o[nt], al0,al1,al2,al3, vh0,vh1);
            }
        }
    }

    if ((lane & 3) == 0) {
        den_s[i0 + (lane >> 2)]     = 1.f / (o[8][0] + EPS_DEN);
        den_s[i0 + 8 + (lane >> 2)] = 1.f / (o[8][2] + EPS_DEN);
    }
    __syncwarp();
    {
        const int m1 = i0 + (lane >> 2);
        const int m2 = m1 + 8;
        const float inv1 = den_s[m1];
        const float inv2 = den_s[m2];
        #pragma unroll
        for (int nt = 0; nt < 8; nt++) {
            int n = nt*8 + 2*(lane & 3);
            float2 t1 = { o[nt][0]*inv1, o[nt][1]*inv1 };
            float2 t2 = { o[nt][2]*inv2, o[nt][3]*inv2 };
            *reinterpret_cast<float2*>(outg + (tok0 + m1)*Dd + n) = t1;
            *reinterpret_cast<float2*>(outg + (tok0 + m2)*Dd + n) = t2;
        }
    }
}

// ---------------------------------------------------------------------------

extern "C" void kernel_launch(void* const* d_in, const int* in_sizes, int n_in,
                              void* d_out, int out_size) {
    const float* q  = (const float*)d_in[0];
    const float* k  = (const float*)d_in[1];
    const float* v  = (const float*)d_in[2];
    const float* om = (const float*)d_in[3];
    float* out = (float*)d_out;

    const int SM2 = 24576 * 4;   // 98304
    cudaFuncSetAttribute(k_proj_mma,  cudaFuncAttributeMaxDynamicSharedMemorySize, SM1T);
    cudaFuncSetAttribute(k_phik_sums, cudaFuncAttributeMaxDynamicSharedMemorySize, SM2);
    cudaFuncSetAttribute(k_out_mma,   cudaFuncAttributeMaxDynamicSharedMemorySize, SM4T);

    k_proj_mma<<<2*NBT, 256, SM1T>>>(q, k, om);
    k_gmax<<<1, 256>>>();
    k_phik_sums<<<NBT, 256, SM2>>>(v);
    k_scan<<<2048 + 32, 256>>>();
    k_out_mma<<<NBT, 256, SM4T>>>(v, out);
}